// round 1
// baseline (speedup 1.0000x reference)
#include <cuda_runtime.h>
#include <math.h>
#include <stdint.h>

#define B_  32
#define NTOK 197
#define NPATCH 196
#define D_  768
#define H_  12
#define DH  64
#define F_  3072
#define L_  12
#define ROWS  (B_*NTOK)    /* 6304 */
#define PROWS (B_*NPATCH)  /* 6272 */

// ---------------- scratch (device globals; no allocation) ----------------
__device__ float g_patches[PROWS * D_];
__device__ float g_wT[D_ * D_];
__device__ float g_emb[PROWS * D_];
__device__ float g_h[ROWS * D_];
__device__ float g_y[ROWS * D_];
__device__ float g_qkv[ROWS * 3 * D_];
__device__ float g_o[ROWS * D_];
__device__ float g_mid[ROWS * F_];

// ---------------- patch extraction ----------------
__global__ void extract_patches_kernel(const float* __restrict__ x, float* __restrict__ patches) {
    const int total = PROWS * D_;
    for (int idx = blockIdx.x * blockDim.x + threadIdx.x; idx < total; idx += gridDim.x * blockDim.x) {
        int row = idx / D_;      // b*196 + t
        int k   = idx % D_;      // cin*256 + py*16 + px
        int b   = row / NPATCH;
        int t   = row % NPATCH;
        int ph  = t / 14, pw = t % 14;
        int cin = k / 256;
        int rem = k % 256;
        int py  = rem / 16, px = rem % 16;
        size_t src = (((size_t)b * 3 + cin) * 224 + (ph * 16 + py)) * 224 + (pw * 16 + px);
        patches[idx] = x[src];
    }
}

// wT[k][n] = conv_w[n][k]   (conv_w viewed as (768, 768) row-major)
__global__ void transpose768_kernel(const float* __restrict__ w, float* __restrict__ wT) {
    const int total = D_ * D_;
    for (int idx = blockIdx.x * blockDim.x + threadIdx.x; idx < total; idx += gridDim.x * blockDim.x) {
        int k = idx / D_, n = idx % D_;
        wT[idx] = w[n * D_ + k];
    }
}

// h[b][0][:] = cls + pos[0];  h[b][1+t][:] = emb[b,t] + pos[1+t]
__global__ void assemble_kernel(const float* __restrict__ emb, const float* __restrict__ cls,
                                const float* __restrict__ pos, float* __restrict__ h) {
    const int total = ROWS * D_;
    for (int idx = blockIdx.x * blockDim.x + threadIdx.x; idx < total; idx += gridDim.x * blockDim.x) {
        int r = idx / D_, d = idx % D_;
        int b = r / NTOK, t = r % NTOK;
        float v = pos[t * D_ + d];
        if (t == 0) v += cls[d];
        else        v += emb[((size_t)b * NPATCH + (t - 1)) * D_ + d];
        h[idx] = v;
    }
}

// ---------------- LayerNorm (one row per block) ----------------
__global__ void ln_kernel(const float* __restrict__ x, const float* __restrict__ w,
                          const float* __restrict__ b, float* __restrict__ y,
                          int D, int inStride, int outStride) {
    const int row = blockIdx.x;
    const float* xr = x + (size_t)row * inStride;
    float* yr = y + (size_t)row * outStride;
    const int tid = threadIdx.x;
    float s = 0.f, q = 0.f;
    for (int i = tid; i < D; i += blockDim.x) {
        float v = xr[i];
        s += v; q += v * v;
    }
    for (int o = 16; o; o >>= 1) {
        s += __shfl_xor_sync(~0u, s, o);
        q += __shfl_xor_sync(~0u, q, o);
    }
    __shared__ float ss[8], sq[8];
    __shared__ float mean_s, rstd_s;
    int wid = tid >> 5, lane = tid & 31;
    if (lane == 0) { ss[wid] = s; sq[wid] = q; }
    __syncthreads();
    if (tid == 0) {
        float ts = 0.f, tq = 0.f;
        for (int i = 0; i < (int)(blockDim.x >> 5); i++) { ts += ss[i]; tq += sq[i]; }
        float m = ts / D;
        float v = tq / D - m * m;
        mean_s = m;
        rstd_s = rsqrtf(v + 1e-6f);
    }
    __syncthreads();
    float m = mean_s, rs = rstd_s;
    for (int i = tid; i < D; i += blockDim.x)
        yr[i] = (xr[i] - m) * rs * w[i] + b[i];
}

// ---------------- SGEMM: C = A(MxK) @ B(KxN) + bias + resid, opt GELU ----------------
// 64x64 tile, BK=16, 256 threads, 4x4 per thread.
__global__ void sgemm_kernel(const float* __restrict__ A, const float* __restrict__ Bm,
                             const float* __restrict__ bias, const float* __restrict__ resid,
                             float* __restrict__ C, int M, int N, int K, int act) {
    __shared__ float As[16][65];
    __shared__ float Bs[16][64];
    const int tid = threadIdx.x;
    const int bm = blockIdx.y * 64, bn = blockIdx.x * 64;
    const int tr = (tid / 16) * 4;
    const int tc = (tid % 16) * 4;
    float acc[4][4] = {};

    const int lar = tid / 4;              // A load row 0..63
    const int lac = (tid % 4) * 4;        // A load col 0..12
    const int lbr = tid / 16;             // B load row 0..15
    const int lbc = (tid % 16) * 4;       // B load col 0..60

    for (int k0 = 0; k0 < K; k0 += 16) {
        {
            float4 v = make_float4(0.f, 0.f, 0.f, 0.f);
            int gr = bm + lar;
            if (gr < M) v = *(const float4*)(A + (size_t)gr * K + k0 + lac);
            As[lac + 0][lar] = v.x;
            As[lac + 1][lar] = v.y;
            As[lac + 2][lar] = v.z;
            As[lac + 3][lar] = v.w;
        }
        {
            float4 v = *(const float4*)(Bm + (size_t)(k0 + lbr) * N + bn + lbc);
            *(float4*)&Bs[lbr][lbc] = v;
        }
        __syncthreads();
#pragma unroll
        for (int kk = 0; kk < 16; kk++) {
            float a0 = As[kk][tr + 0];
            float a1 = As[kk][tr + 1];
            float a2 = As[kk][tr + 2];
            float a3 = As[kk][tr + 3];
            float4 bv = *(const float4*)&Bs[kk][tc];
            acc[0][0] += a0 * bv.x; acc[0][1] += a0 * bv.y; acc[0][2] += a0 * bv.z; acc[0][3] += a0 * bv.w;
            acc[1][0] += a1 * bv.x; acc[1][1] += a1 * bv.y; acc[1][2] += a1 * bv.z; acc[1][3] += a1 * bv.w;
            acc[2][0] += a2 * bv.x; acc[2][1] += a2 * bv.y; acc[2][2] += a2 * bv.z; acc[2][3] += a2 * bv.w;
            acc[3][0] += a3 * bv.x; acc[3][1] += a3 * bv.y; acc[3][2] += a3 * bv.z; acc[3][3] += a3 * bv.w;
        }
        __syncthreads();
    }

#pragma unroll
    for (int i = 0; i < 4; i++) {
        int r = bm + tr + i;
        if (r >= M) continue;
#pragma unroll
        for (int j = 0; j < 4; j++) {
            int c = bn + tc + j;
            float v = acc[i][j];
            if (bias) v += bias[c];
            if (act == 1) v = 0.5f * v * (1.0f + erff(v * 0.70710678118654752f));
            if (resid) v += resid[(size_t)r * N + c];
            C[(size_t)r * N + c] = v;
        }
    }
}

// ---------------- fused attention: one block per (b, h) ----------------
// smem: Ks[197][65], Vs[197][65], qrow[8][64], prow[8][200]
#define ATTN_SMEM ((2 * NTOK * 65 + 8 * 64 + 8 * 200) * (int)sizeof(float))
__global__ void attn_kernel(const float* __restrict__ qkv, float* __restrict__ o) {
    extern __shared__ float smem[];
    float* Ks = smem;                       // 197*65
    float* Vs = Ks + NTOK * 65;             // 197*65
    float* qrow = Vs + NTOK * 65;           // 8*64
    float* prow = qrow + 8 * 64;            // 8*200

    const int bh = blockIdx.x;
    const int b = bh / H_;
    const int h = bh % H_;
    const int tid = threadIdx.x;
    const int lane = tid & 31;
    const int w = tid >> 5;

    // stage K and V
    for (int idx = tid; idx < NTOK * DH; idx += blockDim.x) {
        int m = idx / DH, d = idx % DH;
        size_t base = ((size_t)(b * NTOK + m)) * (3 * D_) + h * DH + d;
        Ks[m * 65 + d] = qkv[base + D_];
        Vs[m * 65 + d] = qkv[base + 2 * D_];
    }
    __syncthreads();

    float* qr = qrow + w * 64;
    float* pr = prow + w * 200;

    for (int n = w; n < NTOK; n += 8) {
        size_t qbase = ((size_t)(b * NTOK + n)) * (3 * D_) + h * DH;
        qr[lane]      = qkv[qbase + lane];
        qr[lane + 32] = qkv[qbase + lane + 32];
        __syncwarp();

        float s[7];
        float mx = -1e30f;
#pragma unroll
        for (int j = 0; j < 7; j++) {
            int m = lane + 32 * j;
            float acc = -1e30f;
            if (m < NTOK) {
                const float* kp = Ks + m * 65;
                acc = 0.f;
#pragma unroll 8
                for (int d = 0; d < DH; d++) acc += qr[d] * kp[d];
                acc *= 0.125f;
            }
            s[j] = acc;
            mx = fmaxf(mx, acc);
        }
        for (int off = 16; off; off >>= 1) mx = fmaxf(mx, __shfl_xor_sync(~0u, mx, off));

        float sum = 0.f;
#pragma unroll
        for (int j = 0; j < 7; j++) {
            int m = lane + 32 * j;
            if (m < NTOK) { s[j] = expf(s[j] - mx); sum += s[j]; }
        }
        for (int off = 16; off; off >>= 1) sum += __shfl_xor_sync(~0u, sum, off);
        float inv = 1.f / sum;

#pragma unroll
        for (int j = 0; j < 7; j++) {
            int m = lane + 32 * j;
            if (m < NTOK) pr[m] = s[j] * inv;
        }
        __syncwarp();

        size_t obase = ((size_t)(b * NTOK + n)) * D_ + h * DH;
#pragma unroll
        for (int d0 = 0; d0 < 2; d0++) {
            int d = lane + 32 * d0;
            float acc = 0.f;
            for (int m = 0; m < NTOK; m++) acc += pr[m] * Vs[m * 65 + d];
            o[obase + d] = acc;
        }
        __syncwarp();
    }
}

// ---------------- host ----------------
extern "C" void kernel_launch(void* const* d_in, const int* in_sizes, int n_in,
                              void* d_out, int out_size) {
    const float* x       = (const float*)d_in[0];
    const float* conv_w  = (const float*)d_in[1];
    const float* conv_b  = (const float*)d_in[2];
    const float* cls_tok = (const float*)d_in[3];
    const float* pos     = (const float*)d_in[4];
    const float* ln1w    = (const float*)d_in[5];
    const float* ln1b    = (const float*)d_in[6];
    const float* qkvw    = (const float*)d_in[7];
    const float* qkvb    = (const float*)d_in[8];
    const float* projw   = (const float*)d_in[9];
    const float* projb   = (const float*)d_in[10];
    const float* ln2w    = (const float*)d_in[11];
    const float* ln2b    = (const float*)d_in[12];
    const float* fc1w    = (const float*)d_in[13];
    const float* fc1b    = (const float*)d_in[14];
    const float* fc2w    = (const float*)d_in[15];
    const float* fc2b    = (const float*)d_in[16];
    const float* lnfw    = (const float*)d_in[17];
    const float* lnfb    = (const float*)d_in[18];

    float *patches, *wT, *emb, *h, *y, *qkv, *o, *mid;
    cudaGetSymbolAddress((void**)&patches, g_patches);
    cudaGetSymbolAddress((void**)&wT,      g_wT);
    cudaGetSymbolAddress((void**)&emb,     g_emb);
    cudaGetSymbolAddress((void**)&h,       g_h);
    cudaGetSymbolAddress((void**)&y,       g_y);
    cudaGetSymbolAddress((void**)&qkv,     g_qkv);
    cudaGetSymbolAddress((void**)&o,       g_o);
    cudaGetSymbolAddress((void**)&mid,     g_mid);

    cudaFuncSetAttribute(attn_kernel, cudaFuncAttributeMaxDynamicSharedMemorySize, ATTN_SMEM);

    // patch embed
    extract_patches_kernel<<<2048, 256>>>(x, patches);
    transpose768_kernel<<<1024, 256>>>(conv_w, wT);
    {
        dim3 g(D_ / 64, (PROWS + 63) / 64);
        sgemm_kernel<<<g, 256>>>(patches, wT, conv_b, nullptr, emb, PROWS, D_, D_, 0);
    }
    assemble_kernel<<<2048, 256>>>(emb, cls_tok, pos, h);

    const int mblocks = (ROWS + 63) / 64; // 99
    for (int l = 0; l < L_; l++) {
        const float* l1w = ln1w + l * D_;
        const float* l1b = ln1b + l * D_;
        const float* qw  = qkvw + (size_t)l * D_ * 3 * D_;
        const float* qb  = qkvb + (size_t)l * 3 * D_;
        const float* pw  = projw + (size_t)l * D_ * D_;
        const float* pb  = projb + (size_t)l * D_;
        const float* l2w = ln2w + l * D_;
        const float* l2b = ln2b + l * D_;
        const float* f1w = fc1w + (size_t)l * D_ * F_;
        const float* f1b = fc1b + (size_t)l * F_;
        const float* f2w = fc2w + (size_t)l * F_ * D_;
        const float* f2b = fc2b + (size_t)l * D_;

        ln_kernel<<<ROWS, 256>>>(h, l1w, l1b, y, D_, D_, D_);
        sgemm_kernel<<<dim3(3 * D_ / 64, mblocks), 256>>>(y, qw, qb, nullptr, qkv, ROWS, 3 * D_, D_, 0);
        attn_kernel<<<B_ * H_, 256, ATTN_SMEM>>>(qkv, o);
        sgemm_kernel<<<dim3(D_ / 64, mblocks), 256>>>(o, pw, pb, h, h, ROWS, D_, D_, 0);
        ln_kernel<<<ROWS, 256>>>(h, l2w, l2b, y, D_, D_, D_);
        sgemm_kernel<<<dim3(F_ / 64, mblocks), 256>>>(y, f1w, f1b, nullptr, mid, ROWS, F_, D_, 1);
        sgemm_kernel<<<dim3(D_ / 64, mblocks), 256>>>(mid, f2w, f2b, h, h, ROWS, D_, F_, 0);
    }

    // final LN on token 0 of each batch -> d_out (1, 32, 768)
    ln_kernel<<<B_, 256>>>(h, lnfw, lnfb, (float*)d_out, D_, NTOK * D_, D_);
}

// round 5
// speedup vs baseline: 2.3016x; 2.3016x over previous
#include <cuda_runtime.h>
#include <cuda_bf16.h>
#include <math.h>
#include <stdint.h>

#define B_  32
#define NTOK 197
#define NPATCH 196
#define D_  768
#define H_  12
#define DH  64
#define F_  3072
#define L_  12
#define ROWS  (B_*NTOK)    /* 6304 */
#define PROWS (B_*NPATCH)  /* 6272 */

typedef __nv_bfloat16 bf16;

// single dynamic-shared symbol for the whole TU
extern __shared__ char dynsmem[];

// ---------------- scratch (device globals; no allocation) ----------------
__device__ float g_emb[PROWS * D_];
__device__ float g_h[ROWS * D_];
__device__ float g_qkv[ROWS * 3 * D_];

__device__ bf16 g_phi[PROWS * D_];
__device__ bf16 g_plo[PROWS * D_];
__device__ bf16 g_cwhi[D_ * D_];
__device__ bf16 g_cwlo[D_ * D_];

__device__ bf16 g_yhi[ROWS * D_];
__device__ bf16 g_ylo[ROWS * D_];
__device__ bf16 g_ohi[ROWS * D_];
__device__ bf16 g_olo[ROWS * D_];
__device__ bf16 g_midhi[ROWS * F_];
__device__ bf16 g_midlo[ROWS * F_];

// transposed + split weights: stored [N][K] per layer
__device__ bf16 g_wqkv_hi[L_ * 3 * D_ * D_];
__device__ bf16 g_wqkv_lo[L_ * 3 * D_ * D_];
__device__ bf16 g_wproj_hi[L_ * D_ * D_];
__device__ bf16 g_wproj_lo[L_ * D_ * D_];
__device__ bf16 g_wfc1_hi[L_ * F_ * D_];
__device__ bf16 g_wfc1_lo[L_ * F_ * D_];
__device__ bf16 g_wfc2_hi[L_ * D_ * F_];
__device__ bf16 g_wfc2_lo[L_ * D_ * F_];

// ---------------- helpers ----------------
__device__ __forceinline__ uint32_t smem_u32(const void* p) {
    uint32_t a;
    asm("{ .reg .u64 t; cvta.to.shared.u64 t, %1; cvt.u32.u64 %0, t; }" : "=r"(a) : "l"(p));
    return a;
}
#define SW128(off) ((off) ^ (((off) >> 3) & 0x70))

#define LDSM_X4(r0, r1, r2, r3, addr) \
    asm volatile("ldmatrix.sync.aligned.m8n8.x4.shared.b16 {%0,%1,%2,%3}, [%4];" \
        : "=r"(r0), "=r"(r1), "=r"(r2), "=r"(r3) : "r"(addr))

#define MMA16816(d, a, b0, b1) \
    asm volatile("mma.sync.aligned.m16n8k16.row.col.f32.bf16.bf16.f32 " \
        "{%0,%1,%2,%3}, {%4,%5,%6,%7}, {%8,%9}, {%0,%1,%2,%3};" \
        : "+f"((d)[0]), "+f"((d)[1]), "+f"((d)[2]), "+f"((d)[3]) \
        : "r"((a)[0]), "r"((a)[1]), "r"((a)[2]), "r"((a)[3]), "r"(b0), "r"(b1))

#define CP_ASYNC16(dst, src, sz) \
    asm volatile("cp.async.cg.shared.global [%0], [%1], 16, %2;" \
        :: "r"(dst), "l"(src), "r"(sz) : "memory")

// ---------------- tensor-core GEMM via mma.sync (3-product bf16 emulation) ----------------
// C[M,N] = A[M,K] @ B[N,K]^T + bias, modes:
//   0 = outf[row*N+col] = v
//   1 = hres[row*N+col] += v  (residual)
//   2 = gelu(v) -> ohi/olo bf16 split
#define GSTAGE 65536
#define GSMEM_SZ (2 * GSTAGE + 1024)

__global__ void __launch_bounds__(256, 1) gemm_mma_kernel(
    const bf16* __restrict__ Ahi, const bf16* __restrict__ Alo,
    const bf16* __restrict__ Bhi, const bf16* __restrict__ Blo,
    const float* __restrict__ bias,
    float* __restrict__ outf, float* __restrict__ hres,
    bf16* __restrict__ ohi, bf16* __restrict__ olo,
    int M, int N, int K, int mode)
{
    const uint32_t sbase = (smem_u32(dynsmem) + 1023) & ~1023u;
    const int tid = threadIdx.x;
    const int bm = blockIdx.y * 128;
    const int bn = blockIdx.x * 128;
    const int NC = K >> 6;
    const int w = tid >> 5, lane = tid & 31;
    const int wm = w & 3, wn = w >> 2;

    const bf16* srcs[4] = { Ahi, Alo, Bhi, Blo };

    float acc[2][8][4];
#pragma unroll
    for (int mt = 0; mt < 2; mt++)
#pragma unroll
        for (int nt = 0; nt < 8; nt++)
#pragma unroll
            for (int r = 0; r < 4; r++) acc[mt][nt][r] = 0.f;

    // ---- stage loader: tiles Ahi|Alo|Bhi|Blo, 128 rows x 64 bf16, SW128 ----
    auto load_stage = [&](int c) {
        const uint32_t sb = sbase + (uint32_t)(c & 1) * GSTAGE;
        const int k0 = c * 64;
#pragma unroll
        for (int t = 0; t < 4; t++) {
#pragma unroll
            for (int i = 0; i < 4; i++) {
                int s = tid + i * 256;
                int r = s >> 3, seg = s & 7;
                int grow = (t < 2) ? (bm + r) : (bn + r);
                int sz = 16;
                if (t < 2 && grow >= M) { grow = 0; sz = 0; }
                const bf16* src = srcs[t] + (size_t)grow * K + k0 + seg * 8;
                uint32_t dst = sb + t * 16384 + SW128((uint32_t)(r * 128 + seg * 16));
                CP_ASYNC16(dst, src, sz);
            }
        }
        asm volatile("cp.async.commit_group;" ::: "memory");
    };

    load_stage(0);

    for (int c = 0; c < NC; c++) {
        if (c + 1 < NC) {
            load_stage(c + 1);
            asm volatile("cp.async.wait_group 1;" ::: "memory");
        } else {
            asm volatile("cp.async.wait_group 0;" ::: "memory");
        }
        __syncthreads();

        const uint32_t sb = sbase + (uint32_t)(c & 1) * GSTAGE;
        const uint32_t sa_hi = sb, sa_lo = sb + 16384;
        const uint32_t sb_hi = sb + 32768, sb_lo = sb + 49152;

#pragma unroll
        for (int k16 = 0; k16 < 4; k16++) {
            const int kc = k16 * 16;
            uint32_t Ah[2][4], Al[2][4];
#pragma unroll
            for (int mt = 0; mt < 2; mt++) {
                uint32_t aoff = SW128((uint32_t)((wm * 32 + mt * 16 + (lane & 15)) * 128
                                                 + (kc + (lane >> 4) * 8) * 2));
                LDSM_X4(Ah[mt][0], Ah[mt][1], Ah[mt][2], Ah[mt][3], sa_hi + aoff);
                LDSM_X4(Al[mt][0], Al[mt][1], Al[mt][2], Al[mt][3], sa_lo + aoff);
            }
            const int sub = lane >> 3, r8 = lane & 7;
            const int nloc = ((sub & 2) ? 8 : 0) + r8;
            const int kloc = kc + (sub & 1) * 8;
#pragma unroll
            for (int ng = 0; ng < 4; ng++) {
                uint32_t boff = SW128((uint32_t)((wn * 64 + ng * 16 + nloc) * 128 + kloc * 2));
                uint32_t Bh4[4], Bl4[4];
                LDSM_X4(Bh4[0], Bh4[1], Bh4[2], Bh4[3], sb_hi + boff);
                LDSM_X4(Bl4[0], Bl4[1], Bl4[2], Bl4[3], sb_lo + boff);
#pragma unroll
                for (int mt = 0; mt < 2; mt++) {
#pragma unroll
                    for (int half = 0; half < 2; half++) {
                        const int nt = ng * 2 + half;
                        MMA16816(acc[mt][nt], Ah[mt], Bh4[half * 2], Bh4[half * 2 + 1]);
                        MMA16816(acc[mt][nt], Ah[mt], Bl4[half * 2], Bl4[half * 2 + 1]);
                        MMA16816(acc[mt][nt], Al[mt], Bh4[half * 2], Bh4[half * 2 + 1]);
                    }
                }
            }
        }
        __syncthreads();
    }

    // ---- epilogue ----
#pragma unroll
    for (int mt = 0; mt < 2; mt++) {
        const int r0 = bm + wm * 32 + mt * 16 + (lane >> 2);
#pragma unroll
        for (int nt = 0; nt < 8; nt++) {
            const int col = bn + wn * 64 + nt * 8 + (lane & 3) * 2;
            const float b0 = bias[col], b1 = bias[col + 1];
#pragma unroll
            for (int rr = 0; rr < 2; rr++) {
                const int row = r0 + rr * 8;
                if (row >= M) continue;
                float v0 = acc[mt][nt][rr * 2 + 0] + b0;
                float v1 = acc[mt][nt][rr * 2 + 1] + b1;
                size_t oi = (size_t)row * N + col;
                if (mode == 0) {
                    outf[oi] = v0; outf[oi + 1] = v1;
                } else if (mode == 1) {
                    hres[oi] += v0; hres[oi + 1] += v1;
                } else {
                    float g0 = 0.5f * v0 * (1.0f + erff(v0 * 0.70710678118654752f));
                    float g1 = 0.5f * v1 * (1.0f + erff(v1 * 0.70710678118654752f));
                    bf16 h0 = __float2bfloat16(g0);
                    bf16 h1 = __float2bfloat16(g1);
                    ohi[oi] = h0; ohi[oi + 1] = h1;
                    olo[oi]     = __float2bfloat16(g0 - __bfloat162float(h0));
                    olo[oi + 1] = __float2bfloat16(g1 - __bfloat162float(h1));
                }
            }
        }
    }
}

// ---------------- weight transpose + bf16 split: W[K,N] -> hiT/loT [N,K] ----------------
__global__ void wsplit_kernel(const float* __restrict__ W, bf16* __restrict__ hiT,
                              bf16* __restrict__ loT, int K, int N) {
    __shared__ float t[32][33];
    int n0 = blockIdx.x * 32, k0 = blockIdx.y * 32;
    int tx = threadIdx.x, ty = threadIdx.y;  // 32 x 8
#pragma unroll
    for (int j = 0; j < 4; j++)
        t[ty + 8 * j][tx] = W[(size_t)(k0 + ty + 8 * j) * N + n0 + tx];
    __syncthreads();
#pragma unroll
    for (int j = 0; j < 4; j++) {
        int n = n0 + ty + 8 * j, k = k0 + tx;
        float v = t[tx][ty + 8 * j];
        bf16 hi = __float2bfloat16(v);
        size_t oi = (size_t)n * K + k;
        hiT[oi] = hi;
        loT[oi] = __float2bfloat16(v - __bfloat162float(hi));
    }
}

// plain split (already [N][K]): conv_w
__global__ void split_kernel(const float* __restrict__ W, bf16* __restrict__ hi,
                             bf16* __restrict__ lo, int total) {
    for (int i = blockIdx.x * blockDim.x + threadIdx.x; i < total; i += gridDim.x * blockDim.x) {
        float v = W[i];
        bf16 h = __float2bfloat16(v);
        hi[i] = h;
        lo[i] = __float2bfloat16(v - __bfloat162float(h));
    }
}

// ---------------- patch extraction (bf16 hi/lo split) ----------------
__global__ void extract_patches_kernel(const float* __restrict__ x,
                                       bf16* __restrict__ phi, bf16* __restrict__ plo) {
    const int total = PROWS * D_;
    for (int idx = blockIdx.x * blockDim.x + threadIdx.x; idx < total; idx += gridDim.x * blockDim.x) {
        int row = idx / D_;
        int k   = idx % D_;
        int b   = row / NPATCH;
        int t   = row % NPATCH;
        int ph  = t / 14, pw = t % 14;
        int cin = k / 256;
        int rem = k % 256;
        int py  = rem / 16, px = rem % 16;
        size_t src = (((size_t)b * 3 + cin) * 224 + (ph * 16 + py)) * 224 + (pw * 16 + px);
        float v = x[src];
        bf16 h = __float2bfloat16(v);
        phi[idx] = h;
        plo[idx] = __float2bfloat16(v - __bfloat162float(h));
    }
}

__global__ void assemble_kernel(const float* __restrict__ emb, const float* __restrict__ cls,
                                const float* __restrict__ pos, float* __restrict__ h) {
    const int total = ROWS * D_;
    for (int idx = blockIdx.x * blockDim.x + threadIdx.x; idx < total; idx += gridDim.x * blockDim.x) {
        int r = idx / D_, d = idx % D_;
        int t = r % NTOK;
        int b = r / NTOK;
        float v = pos[t * D_ + d];
        if (t == 0) v += cls[d];
        else        v += emb[((size_t)b * NPATCH + (t - 1)) * D_ + d];
        h[idx] = v;
    }
}

// ---------------- LayerNorm ----------------
__global__ void ln_kernel(const float* __restrict__ x, const float* __restrict__ w,
                          const float* __restrict__ b, float* __restrict__ y,
                          int D, int inStride, int outStride) {
    const int row = blockIdx.x;
    const float* xr = x + (size_t)row * inStride;
    float* yr = y + (size_t)row * outStride;
    const int tid = threadIdx.x;
    float s = 0.f, q = 0.f;
    for (int i = tid; i < D; i += blockDim.x) { float v = xr[i]; s += v; q += v * v; }
    for (int o = 16; o; o >>= 1) { s += __shfl_xor_sync(~0u, s, o); q += __shfl_xor_sync(~0u, q, o); }
    __shared__ float ss[8], sq[8], mean_s, rstd_s;
    int wid = tid >> 5, lane = tid & 31;
    if (lane == 0) { ss[wid] = s; sq[wid] = q; }
    __syncthreads();
    if (tid == 0) {
        float ts = 0.f, tq = 0.f;
        for (int i = 0; i < (int)(blockDim.x >> 5); i++) { ts += ss[i]; tq += sq[i]; }
        float m = ts / D;
        mean_s = m;
        rstd_s = rsqrtf(tq / D - m * m + 1e-6f);
    }
    __syncthreads();
    float m = mean_s, rs = rstd_s;
    for (int i = tid; i < D; i += blockDim.x)
        yr[i] = (xr[i] - m) * rs * w[i] + b[i];
}

// LayerNorm writing bf16 hi/lo split
__global__ void ln_split_kernel(const float* __restrict__ x, const float* __restrict__ w,
                                const float* __restrict__ b,
                                bf16* __restrict__ yhi, bf16* __restrict__ ylo) {
    const int row = blockIdx.x;
    const float* xr = x + (size_t)row * D_;
    const int tid = threadIdx.x;
    float s = 0.f, q = 0.f;
    for (int i = tid; i < D_; i += blockDim.x) { float v = xr[i]; s += v; q += v * v; }
    for (int o = 16; o; o >>= 1) { s += __shfl_xor_sync(~0u, s, o); q += __shfl_xor_sync(~0u, q, o); }
    __shared__ float ss[8], sq[8], mean_s, rstd_s;
    int wid = tid >> 5, lane = tid & 31;
    if (lane == 0) { ss[wid] = s; sq[wid] = q; }
    __syncthreads();
    if (tid == 0) {
        float ts = 0.f, tq = 0.f;
        for (int i = 0; i < (int)(blockDim.x >> 5); i++) { ts += ss[i]; tq += sq[i]; }
        float m = ts / D_;
        mean_s = m;
        rstd_s = rsqrtf(tq / D_ - m * m + 1e-6f);
    }
    __syncthreads();
    float m = mean_s, rs = rstd_s;
    for (int i = tid; i < D_; i += blockDim.x) {
        float v = (xr[i] - m) * rs * w[i] + b[i];
        bf16 hi = __float2bfloat16(v);
        size_t oi = (size_t)row * D_ + i;
        yhi[oi] = hi;
        ylo[oi] = __float2bfloat16(v - __bfloat162float(hi));
    }
}

// ---------------- fused attention (fp32, bf16-split output) ----------------
#define ATTN_SMEM ((2 * NTOK * 65 + 8 * 64 + 8 * 200) * (int)sizeof(float))
__global__ void attn_kernel(const float* __restrict__ qkv,
                            bf16* __restrict__ ohi, bf16* __restrict__ olo) {
    float* smem = (float*)dynsmem;
    float* Ks = smem;
    float* Vs = Ks + NTOK * 65;
    float* qrow = Vs + NTOK * 65;
    float* prow = qrow + 8 * 64;

    const int bh = blockIdx.x;
    const int b = bh / H_;
    const int h = bh % H_;
    const int tid = threadIdx.x;
    const int lane = tid & 31;
    const int w = tid >> 5;

    for (int idx = tid; idx < NTOK * DH; idx += blockDim.x) {
        int m = idx / DH, d = idx % DH;
        size_t base = ((size_t)(b * NTOK + m)) * (3 * D_) + h * DH + d;
        Ks[m * 65 + d] = qkv[base + D_];
        Vs[m * 65 + d] = qkv[base + 2 * D_];
    }
    __syncthreads();

    float* qr = qrow + w * 64;
    float* pr = prow + w * 200;

    for (int n = w; n < NTOK; n += 8) {
        size_t qbase = ((size_t)(b * NTOK + n)) * (3 * D_) + h * DH;
        qr[lane]      = qkv[qbase + lane];
        qr[lane + 32] = qkv[qbase + lane + 32];
        __syncwarp();

        float s[7];
        float mx = -1e30f;
#pragma unroll
        for (int j = 0; j < 7; j++) {
            int m = lane + 32 * j;
            float acc = -1e30f;
            if (m < NTOK) {
                const float* kp = Ks + m * 65;
                acc = 0.f;
#pragma unroll 8
                for (int d = 0; d < DH; d++) acc += qr[d] * kp[d];
                acc *= 0.125f;
            }
            s[j] = acc;
            mx = fmaxf(mx, acc);
        }
        for (int off = 16; off; off >>= 1) mx = fmaxf(mx, __shfl_xor_sync(~0u, mx, off));

        float sum = 0.f;
#pragma unroll
        for (int j = 0; j < 7; j++) {
            int m = lane + 32 * j;
            if (m < NTOK) { s[j] = expf(s[j] - mx); sum += s[j]; }
        }
        for (int off = 16; off; off >>= 1) sum += __shfl_xor_sync(~0u, sum, off);
        float inv = 1.f / sum;

#pragma unroll
        for (int j = 0; j < 7; j++) {
            int m = lane + 32 * j;
            if (m < NTOK) pr[m] = s[j] * inv;
        }
        __syncwarp();

        size_t obase = ((size_t)(b * NTOK + n)) * D_ + h * DH;
#pragma unroll
        for (int d0 = 0; d0 < 2; d0++) {
            int d = lane + 32 * d0;
            float acc = 0.f;
            for (int m = 0; m < NTOK; m++) acc += pr[m] * Vs[m * 65 + d];
            bf16 hi = __float2bfloat16(acc);
            ohi[obase + d] = hi;
            olo[obase + d] = __float2bfloat16(acc - __bfloat162float(hi));
        }
        __syncwarp();
    }
}

// ---------------- host ----------------
extern "C" void kernel_launch(void* const* d_in, const int* in_sizes, int n_in,
                              void* d_out, int out_size) {
    const float* x       = (const float*)d_in[0];
    const float* conv_w  = (const float*)d_in[1];
    const float* conv_b  = (const float*)d_in[2];
    const float* cls_tok = (const float*)d_in[3];
    const float* pos     = (const float*)d_in[4];
    const float* ln1w    = (const float*)d_in[5];
    const float* ln1b    = (const float*)d_in[6];
    const float* qkvw    = (const float*)d_in[7];
    const float* qkvb    = (const float*)d_in[8];
    const float* projw   = (const float*)d_in[9];
    const float* projb   = (const float*)d_in[10];
    const float* ln2w    = (const float*)d_in[11];
    const float* ln2b    = (const float*)d_in[12];
    const float* fc1w    = (const float*)d_in[13];
    const float* fc1b    = (const float*)d_in[14];
    const float* fc2w    = (const float*)d_in[15];
    const float* fc2b    = (const float*)d_in[16];
    const float* lnfw    = (const float*)d_in[17];
    const float* lnfb    = (const float*)d_in[18];

    float *emb, *h, *qkv;
    bf16 *phi, *plo, *cwhi, *cwlo;
    bf16 *yhi, *ylo, *ohi, *olo, *midhi, *midlo;
    bf16 *wq_h, *wq_l, *wp_h, *wp_l, *w1_h, *w1_l, *w2_h, *w2_l;
    cudaGetSymbolAddress((void**)&emb,     g_emb);
    cudaGetSymbolAddress((void**)&h,       g_h);
    cudaGetSymbolAddress((void**)&qkv,     g_qkv);
    cudaGetSymbolAddress((void**)&phi,     g_phi);
    cudaGetSymbolAddress((void**)&plo,     g_plo);
    cudaGetSymbolAddress((void**)&cwhi,    g_cwhi);
    cudaGetSymbolAddress((void**)&cwlo,    g_cwlo);
    cudaGetSymbolAddress((void**)&yhi,     g_yhi);
    cudaGetSymbolAddress((void**)&ylo,     g_ylo);
    cudaGetSymbolAddress((void**)&ohi,     g_ohi);
    cudaGetSymbolAddress((void**)&olo,     g_olo);
    cudaGetSymbolAddress((void**)&midhi,   g_midhi);
    cudaGetSymbolAddress((void**)&midlo,   g_midlo);
    cudaGetSymbolAddress((void**)&wq_h,    g_wqkv_hi);
    cudaGetSymbolAddress((void**)&wq_l,    g_wqkv_lo);
    cudaGetSymbolAddress((void**)&wp_h,    g_wproj_hi);
    cudaGetSymbolAddress((void**)&wp_l,    g_wproj_lo);
    cudaGetSymbolAddress((void**)&w1_h,    g_wfc1_hi);
    cudaGetSymbolAddress((void**)&w1_l,    g_wfc1_lo);
    cudaGetSymbolAddress((void**)&w2_h,    g_wfc2_hi);
    cudaGetSymbolAddress((void**)&w2_l,    g_wfc2_lo);

    cudaFuncSetAttribute(attn_kernel, cudaFuncAttributeMaxDynamicSharedMemorySize, ATTN_SMEM);
    cudaFuncSetAttribute(gemm_mma_kernel, cudaFuncAttributeMaxDynamicSharedMemorySize, GSMEM_SZ);

    // ---- weight conversion (transpose + bf16 split), once per launch ----
    {
        dim3 blk(32, 8);
        for (int l = 0; l < L_; l++) {
            wsplit_kernel<<<dim3(3 * D_ / 32, D_ / 32), blk>>>(
                qkvw + (size_t)l * D_ * 3 * D_, wq_h + (size_t)l * 3 * D_ * D_,
                wq_l + (size_t)l * 3 * D_ * D_, D_, 3 * D_);
            wsplit_kernel<<<dim3(D_ / 32, D_ / 32), blk>>>(
                projw + (size_t)l * D_ * D_, wp_h + (size_t)l * D_ * D_,
                wp_l + (size_t)l * D_ * D_, D_, D_);
            wsplit_kernel<<<dim3(F_ / 32, D_ / 32), blk>>>(
                fc1w + (size_t)l * D_ * F_, w1_h + (size_t)l * F_ * D_,
                w1_l + (size_t)l * F_ * D_, D_, F_);
            wsplit_kernel<<<dim3(D_ / 32, F_ / 32), blk>>>(
                fc2w + (size_t)l * F_ * D_, w2_h + (size_t)l * D_ * F_,
                w2_l + (size_t)l * D_ * F_, F_, D_);
        }
        split_kernel<<<1024, 256>>>(conv_w, cwhi, cwlo, D_ * D_);
    }

    // ---- patch embed (tensor core) ----
    extract_patches_kernel<<<2048, 256>>>(x, phi, plo);
    gemm_mma_kernel<<<dim3(D_ / 128, (PROWS + 127) / 128), 256, GSMEM_SZ>>>(
        phi, plo, cwhi, cwlo, conv_b, emb, nullptr, nullptr, nullptr,
        PROWS, D_, D_, 0);
    assemble_kernel<<<2048, 256>>>(emb, cls_tok, pos, h);

    const int mb = (ROWS + 127) / 128;  // 50
    for (int l = 0; l < L_; l++) {
        ln_split_kernel<<<ROWS, 256>>>(h, ln1w + l * D_, ln1b + l * D_, yhi, ylo);
        gemm_mma_kernel<<<dim3(3 * D_ / 128, mb), 256, GSMEM_SZ>>>(
            yhi, ylo, wq_h + (size_t)l * 3 * D_ * D_, wq_l + (size_t)l * 3 * D_ * D_,
            qkvb + (size_t)l * 3 * D_, qkv, nullptr, nullptr, nullptr,
            ROWS, 3 * D_, D_, 0);
        attn_kernel<<<B_ * H_, 256, ATTN_SMEM>>>(qkv, ohi, olo);
        gemm_mma_kernel<<<dim3(D_ / 128, mb), 256, GSMEM_SZ>>>(
            ohi, olo, wp_h + (size_t)l * D_ * D_, wp_l + (size_t)l * D_ * D_,
            projb + (size_t)l * D_, nullptr, h, nullptr, nullptr,
            ROWS, D_, D_, 1);
        ln_split_kernel<<<ROWS, 256>>>(h, ln2w + l * D_, ln2b + l * D_, yhi, ylo);
        gemm_mma_kernel<<<dim3(F_ / 128, mb), 256, GSMEM_SZ>>>(
            yhi, ylo, w1_h + (size_t)l * F_ * D_, w1_l + (size_t)l * F_ * D_,
            fc1b + (size_t)l * F_, nullptr, nullptr, midhi, midlo,
            ROWS, F_, D_, 2);
        gemm_mma_kernel<<<dim3(D_ / 128, mb), 256, GSMEM_SZ>>>(
            midhi, midlo, w2_h + (size_t)l * D_ * F_, w2_l + (size_t)l * D_ * F_,
            fc2b + (size_t)l * D_, nullptr, h, nullptr, nullptr,
            ROWS, D_, F_, 1);
    }

    ln_kernel<<<B_, 256>>>(h, lnfw, lnfb, (float*)d_out, D_, NTOK * D_, D_);
}

// round 6
// speedup vs baseline: 3.9400x; 1.7119x over previous
#include <cuda_runtime.h>
#include <cuda_fp16.h>
#include <math.h>
#include <stdint.h>

#define B_  32
#define NTOK 197
#define NPATCH 196
#define D_  768
#define H_  12
#define DH  64
#define F_  3072
#define L_  12
#define ROWS  (B_*NTOK)    /* 6304 */
#define PROWS (B_*NPATCH)  /* 6272 */

typedef __half h16;

// single dynamic-shared symbol for the whole TU
extern __shared__ char dynsmem[];

// ---------------- scratch (device globals; no allocation) ----------------
__device__ float g_emb[PROWS * D_];
__device__ float g_h[ROWS * D_];
__device__ float g_qkv[ROWS * 3 * D_];

__device__ h16 g_p16[PROWS * D_];
__device__ h16 g_cw16[D_ * D_];

__device__ h16 g_y16[ROWS * D_];
__device__ h16 g_o16[ROWS * D_];
__device__ h16 g_mid16[ROWS * F_];

// transposed weights: stored [N][K] per layer
__device__ h16 g_wqkv[L_ * 3 * D_ * D_];
__device__ h16 g_wproj[L_ * D_ * D_];
__device__ h16 g_wfc1[L_ * F_ * D_];
__device__ h16 g_wfc2[L_ * D_ * F_];

// ---------------- helpers ----------------
__device__ __forceinline__ uint32_t smem_u32(const void* p) {
    uint32_t a;
    asm("{ .reg .u64 t; cvta.to.shared.u64 t, %1; cvt.u32.u64 %0, t; }" : "=r"(a) : "l"(p));
    return a;
}
#define SW128(off) ((off) ^ (((off) >> 3) & 0x70))

#define LDSM_X4(r0, r1, r2, r3, addr) \
    asm volatile("ldmatrix.sync.aligned.m8n8.x4.shared.b16 {%0,%1,%2,%3}, [%4];" \
        : "=r"(r0), "=r"(r1), "=r"(r2), "=r"(r3) : "r"(addr))

#define MMA16816(d, a, b0, b1) \
    asm volatile("mma.sync.aligned.m16n8k16.row.col.f32.f16.f16.f32 " \
        "{%0,%1,%2,%3}, {%4,%5,%6,%7}, {%8,%9}, {%0,%1,%2,%3};" \
        : "+f"((d)[0]), "+f"((d)[1]), "+f"((d)[2]), "+f"((d)[3]) \
        : "r"((a)[0]), "r"((a)[1]), "r"((a)[2]), "r"((a)[3]), "r"(b0), "r"(b1))

#define CP_ASYNC16(dst, src, sz) \
    asm volatile("cp.async.cg.shared.global [%0], [%1], 16, %2;" \
        :: "r"(dst), "l"(src), "r"(sz) : "memory")

// ---------------- tensor-core GEMM via mma.sync (fp16 in, fp32 accum) ----------------
// C[M,N] = A[M,K] @ B[N,K]^T + bias, modes:
//   0 = outf[row*N+col] = v
//   1 = hres[row*N+col] += v  (residual)
//   2 = gelu(v) -> o16 fp16
#define GSTAGE 32768
#define GSMEM_SZ (2 * GSTAGE + 1024)

__global__ void __launch_bounds__(256, 2) gemm_mma_kernel(
    const h16* __restrict__ A, const h16* __restrict__ Bw,
    const float* __restrict__ bias,
    float* __restrict__ outf, float* __restrict__ hres,
    h16* __restrict__ o16,
    int M, int N, int K, int mode)
{
    const uint32_t sbase = (smem_u32(dynsmem) + 1023) & ~1023u;
    const int tid = threadIdx.x;
    const int bm = blockIdx.y * 128;
    const int bn = blockIdx.x * 128;
    const int NC = K >> 6;
    const int w = tid >> 5, lane = tid & 31;
    const int wm = w & 3, wn = w >> 2;

    float acc[2][8][4];
#pragma unroll
    for (int mt = 0; mt < 2; mt++)
#pragma unroll
        for (int nt = 0; nt < 8; nt++)
#pragma unroll
            for (int r = 0; r < 4; r++) acc[mt][nt][r] = 0.f;

    // ---- stage loader: tiles A|B, 128 rows x 64 fp16 each, SW128 ----
    auto load_stage = [&](int c) {
        const uint32_t sb = sbase + (uint32_t)(c & 1) * GSTAGE;
        const int k0 = c * 64;
#pragma unroll
        for (int t = 0; t < 2; t++) {
#pragma unroll
            for (int i = 0; i < 4; i++) {
                int s = tid + i * 256;
                int r = s >> 3, seg = s & 7;
                int grow = (t == 0) ? (bm + r) : (bn + r);
                int sz = 16;
                if (t == 0 && grow >= M) { grow = 0; sz = 0; }
                const h16* src = (t == 0 ? A : Bw) + (size_t)grow * K + k0 + seg * 8;
                uint32_t dst = sb + t * 16384 + SW128((uint32_t)(r * 128 + seg * 16));
                CP_ASYNC16(dst, src, sz);
            }
        }
        asm volatile("cp.async.commit_group;" ::: "memory");
    };

    load_stage(0);

    for (int c = 0; c < NC; c++) {
        if (c + 1 < NC) {
            load_stage(c + 1);
            asm volatile("cp.async.wait_group 1;" ::: "memory");
        } else {
            asm volatile("cp.async.wait_group 0;" ::: "memory");
        }
        __syncthreads();

        const uint32_t sb = sbase + (uint32_t)(c & 1) * GSTAGE;
        const uint32_t sa = sb, sbw = sb + 16384;

#pragma unroll
        for (int k16 = 0; k16 < 4; k16++) {
            const int kc = k16 * 16;
            uint32_t Af[2][4];
#pragma unroll
            for (int mt = 0; mt < 2; mt++) {
                uint32_t aoff = SW128((uint32_t)((wm * 32 + mt * 16 + (lane & 15)) * 128
                                                 + (kc + (lane >> 4) * 8) * 2));
                LDSM_X4(Af[mt][0], Af[mt][1], Af[mt][2], Af[mt][3], sa + aoff);
            }
            const int sub = lane >> 3, r8 = lane & 7;
            const int nloc = ((sub & 2) ? 8 : 0) + r8;
            const int kloc = kc + (sub & 1) * 8;
#pragma unroll
            for (int ng = 0; ng < 4; ng++) {
                uint32_t boff = SW128((uint32_t)((wn * 64 + ng * 16 + nloc) * 128 + kloc * 2));
                uint32_t Bf[4];
                LDSM_X4(Bf[0], Bf[1], Bf[2], Bf[3], sbw + boff);
#pragma unroll
                for (int mt = 0; mt < 2; mt++) {
#pragma unroll
                    for (int half = 0; half < 2; half++) {
                        const int nt = ng * 2 + half;
                        MMA16816(acc[mt][nt], Af[mt], Bf[half * 2], Bf[half * 2 + 1]);
                    }
                }
            }
        }
        __syncthreads();
    }

    // ---- epilogue ----
#pragma unroll
    for (int mt = 0; mt < 2; mt++) {
        const int r0 = bm + wm * 32 + mt * 16 + (lane >> 2);
#pragma unroll
        for (int nt = 0; nt < 8; nt++) {
            const int col = bn + wn * 64 + nt * 8 + (lane & 3) * 2;
            const float b0 = bias[col], b1 = bias[col + 1];
#pragma unroll
            for (int rr = 0; rr < 2; rr++) {
                const int row = r0 + rr * 8;
                if (row >= M) continue;
                float v0 = acc[mt][nt][rr * 2 + 0] + b0;
                float v1 = acc[mt][nt][rr * 2 + 1] + b1;
                size_t oi = (size_t)row * N + col;
                if (mode == 0) {
                    outf[oi] = v0; outf[oi + 1] = v1;
                } else if (mode == 1) {
                    hres[oi] += v0; hres[oi + 1] += v1;
                } else {
                    float g0 = 0.5f * v0 * (1.0f + erff(v0 * 0.70710678118654752f));
                    float g1 = 0.5f * v1 * (1.0f + erff(v1 * 0.70710678118654752f));
                    o16[oi] = __float2half(g0);
                    o16[oi + 1] = __float2half(g1);
                }
            }
        }
    }
}

// ---------------- weight transpose + fp16: W[K,N] -> W16T [N,K] ----------------
__global__ void wsplit_kernel(const float* __restrict__ W, h16* __restrict__ WT,
                              int K, int N) {
    __shared__ float t[32][33];
    int n0 = blockIdx.x * 32, k0 = blockIdx.y * 32;
    int tx = threadIdx.x, ty = threadIdx.y;  // 32 x 8
#pragma unroll
    for (int j = 0; j < 4; j++)
        t[ty + 8 * j][tx] = W[(size_t)(k0 + ty + 8 * j) * N + n0 + tx];
    __syncthreads();
#pragma unroll
    for (int j = 0; j < 4; j++) {
        int n = n0 + ty + 8 * j, k = k0 + tx;
        WT[(size_t)n * K + k] = __float2half(t[tx][ty + 8 * j]);
    }
}

// plain convert (already [N][K]): conv_w
__global__ void split_kernel(const float* __restrict__ W, h16* __restrict__ o, int total) {
    for (int i = blockIdx.x * blockDim.x + threadIdx.x; i < total; i += gridDim.x * blockDim.x)
        o[i] = __float2half(W[i]);
}

// ---------------- patch extraction (fp16) ----------------
__global__ void extract_patches_kernel(const float* __restrict__ x, h16* __restrict__ p16) {
    const int total = PROWS * D_;
    for (int idx = blockIdx.x * blockDim.x + threadIdx.x; idx < total; idx += gridDim.x * blockDim.x) {
        int row = idx / D_;
        int k   = idx % D_;
        int b   = row / NPATCH;
        int t   = row % NPATCH;
        int ph  = t / 14, pw = t % 14;
        int cin = k / 256;
        int rem = k % 256;
        int py  = rem / 16, px = rem % 16;
        size_t src = (((size_t)b * 3 + cin) * 224 + (ph * 16 + py)) * 224 + (pw * 16 + px);
        p16[idx] = __float2half(x[src]);
    }
}

__global__ void assemble_kernel(const float* __restrict__ emb, const float* __restrict__ cls,
                                const float* __restrict__ pos, float* __restrict__ h) {
    const int total = ROWS * D_;
    for (int idx = blockIdx.x * blockDim.x + threadIdx.x; idx < total; idx += gridDim.x * blockDim.x) {
        int r = idx / D_, d = idx % D_;
        int t = r % NTOK;
        int b = r / NTOK;
        float v = pos[t * D_ + d];
        if (t == 0) v += cls[d];
        else        v += emb[((size_t)b * NPATCH + (t - 1)) * D_ + d];
        h[idx] = v;
    }
}

// ---------------- LayerNorm (fp32 out, for final) ----------------
__global__ void ln_kernel(const float* __restrict__ x, const float* __restrict__ w,
                          const float* __restrict__ b, float* __restrict__ y,
                          int D, int inStride, int outStride) {
    const int row = blockIdx.x;
    const float* xr = x + (size_t)row * inStride;
    float* yr = y + (size_t)row * outStride;
    const int tid = threadIdx.x;
    float s = 0.f, q = 0.f;
    for (int i = tid; i < D; i += blockDim.x) { float v = xr[i]; s += v; q += v * v; }
    for (int o = 16; o; o >>= 1) { s += __shfl_xor_sync(~0u, s, o); q += __shfl_xor_sync(~0u, q, o); }
    __shared__ float ss[8], sq[8], mean_s, rstd_s;
    int wid = tid >> 5, lane = tid & 31;
    if (lane == 0) { ss[wid] = s; sq[wid] = q; }
    __syncthreads();
    if (tid == 0) {
        float ts = 0.f, tq = 0.f;
        for (int i = 0; i < (int)(blockDim.x >> 5); i++) { ts += ss[i]; tq += sq[i]; }
        float m = ts / D;
        mean_s = m;
        rstd_s = rsqrtf(tq / D - m * m + 1e-6f);
    }
    __syncthreads();
    float m = mean_s, rs = rstd_s;
    for (int i = tid; i < D; i += blockDim.x)
        yr[i] = (xr[i] - m) * rs * w[i] + b[i];
}

// LayerNorm writing fp16
__global__ void ln_h_kernel(const float* __restrict__ x, const float* __restrict__ w,
                            const float* __restrict__ b, h16* __restrict__ y16) {
    const int row = blockIdx.x;
    const float* xr = x + (size_t)row * D_;
    const int tid = threadIdx.x;
    float s = 0.f, q = 0.f;
    for (int i = tid; i < D_; i += blockDim.x) { float v = xr[i]; s += v; q += v * v; }
    for (int o = 16; o; o >>= 1) { s += __shfl_xor_sync(~0u, s, o); q += __shfl_xor_sync(~0u, q, o); }
    __shared__ float ss[8], sq[8], mean_s, rstd_s;
    int wid = tid >> 5, lane = tid & 31;
    if (lane == 0) { ss[wid] = s; sq[wid] = q; }
    __syncthreads();
    if (tid == 0) {
        float ts = 0.f, tq = 0.f;
        for (int i = 0; i < (int)(blockDim.x >> 5); i++) { ts += ss[i]; tq += sq[i]; }
        float m = ts / D_;
        mean_s = m;
        rstd_s = rsqrtf(tq / D_ - m * m + 1e-6f);
    }
    __syncthreads();
    float m = mean_s, rs = rstd_s;
    for (int i = tid; i < D_; i += blockDim.x) {
        float v = (xr[i] - m) * rs * w[i] + b[i];
        y16[(size_t)row * D_ + i] = __float2half(v);
    }
}

// ---------------- fused attention (fp32 compute, fp16 output) ----------------
#define ATTN_SMEM ((2 * NTOK * 65 + 8 * 64 + 8 * 200) * (int)sizeof(float))
__global__ void attn_kernel(const float* __restrict__ qkv, h16* __restrict__ o16) {
    float* smem = (float*)dynsmem;
    float* Ks = smem;
    float* Vs = Ks + NTOK * 65;
    float* qrow = Vs + NTOK * 65;
    float* prow = qrow + 8 * 64;

    const int bh = blockIdx.x;
    const int b = bh / H_;
    const int h = bh % H_;
    const int tid = threadIdx.x;
    const int lane = tid & 31;
    const int w = tid >> 5;

    for (int idx = tid; idx < NTOK * DH; idx += blockDim.x) {
        int m = idx / DH, d = idx % DH;
        size_t base = ((size_t)(b * NTOK + m)) * (3 * D_) + h * DH + d;
        Ks[m * 65 + d] = qkv[base + D_];
        Vs[m * 65 + d] = qkv[base + 2 * D_];
    }
    __syncthreads();

    float* qr = qrow + w * 64;
    float* pr = prow + w * 200;

    for (int n = w; n < NTOK; n += 8) {
        size_t qbase = ((size_t)(b * NTOK + n)) * (3 * D_) + h * DH;
        qr[lane]      = qkv[qbase + lane];
        qr[lane + 32] = qkv[qbase + lane + 32];
        __syncwarp();

        float s[7];
        float mx = -1e30f;
#pragma unroll
        for (int j = 0; j < 7; j++) {
            int m = lane + 32 * j;
            float acc = -1e30f;
            if (m < NTOK) {
                const float* kp = Ks + m * 65;
                acc = 0.f;
#pragma unroll 8
                for (int d = 0; d < DH; d++) acc += qr[d] * kp[d];
                acc *= 0.125f;
            }
            s[j] = acc;
            mx = fmaxf(mx, acc);
        }
        for (int off = 16; off; off >>= 1) mx = fmaxf(mx, __shfl_xor_sync(~0u, mx, off));

        float sum = 0.f;
#pragma unroll
        for (int j = 0; j < 7; j++) {
            int m = lane + 32 * j;
            if (m < NTOK) { s[j] = expf(s[j] - mx); sum += s[j]; }
        }
        for (int off = 16; off; off >>= 1) sum += __shfl_xor_sync(~0u, sum, off);
        float inv = 1.f / sum;

#pragma unroll
        for (int j = 0; j < 7; j++) {
            int m = lane + 32 * j;
            if (m < NTOK) pr[m] = s[j] * inv;
        }
        __syncwarp();

        size_t obase = ((size_t)(b * NTOK + n)) * D_ + h * DH;
#pragma unroll
        for (int d0 = 0; d0 < 2; d0++) {
            int d = lane + 32 * d0;
            float acc = 0.f;
            for (int m = 0; m < NTOK; m++) acc += pr[m] * Vs[m * 65 + d];
            o16[obase + d] = __float2half(acc);
        }
        __syncwarp();
    }
}

// ---------------- host ----------------
extern "C" void kernel_launch(void* const* d_in, const int* in_sizes, int n_in,
                              void* d_out, int out_size) {
    const float* x       = (const float*)d_in[0];
    const float* conv_w  = (const float*)d_in[1];
    const float* conv_b  = (const float*)d_in[2];
    const float* cls_tok = (const float*)d_in[3];
    const float* pos     = (const float*)d_in[4];
    const float* ln1w    = (const float*)d_in[5];
    const float* ln1b    = (const float*)d_in[6];
    const float* qkvw    = (const float*)d_in[7];
    const float* qkvb    = (const float*)d_in[8];
    const float* projw   = (const float*)d_in[9];
    const float* projb   = (const float*)d_in[10];
    const float* ln2w    = (const float*)d_in[11];
    const float* ln2b    = (const float*)d_in[12];
    const float* fc1w    = (const float*)d_in[13];
    const float* fc1b    = (const float*)d_in[14];
    const float* fc2w    = (const float*)d_in[15];
    const float* fc2b    = (const float*)d_in[16];
    const float* lnfw    = (const float*)d_in[17];
    const float* lnfb    = (const float*)d_in[18];

    float *emb, *h, *qkv;
    h16 *p16, *cw16, *y16, *o16, *mid16;
    h16 *wq, *wp, *w1, *w2;
    cudaGetSymbolAddress((void**)&emb,   g_emb);
    cudaGetSymbolAddress((void**)&h,     g_h);
    cudaGetSymbolAddress((void**)&qkv,   g_qkv);
    cudaGetSymbolAddress((void**)&p16,   g_p16);
    cudaGetSymbolAddress((void**)&cw16,  g_cw16);
    cudaGetSymbolAddress((void**)&y16,   g_y16);
    cudaGetSymbolAddress((void**)&o16,   g_o16);
    cudaGetSymbolAddress((void**)&mid16, g_mid16);
    cudaGetSymbolAddress((void**)&wq,    g_wqkv);
    cudaGetSymbolAddress((void**)&wp,    g_wproj);
    cudaGetSymbolAddress((void**)&w1,    g_wfc1);
    cudaGetSymbolAddress((void**)&w2,    g_wfc2);

    cudaFuncSetAttribute(attn_kernel, cudaFuncAttributeMaxDynamicSharedMemorySize, ATTN_SMEM);
    cudaFuncSetAttribute(gemm_mma_kernel, cudaFuncAttributeMaxDynamicSharedMemorySize, GSMEM_SZ);

    // ---- weight conversion (transpose + fp16), once per launch ----
    {
        dim3 blk(32, 8);
        for (int l = 0; l < L_; l++) {
            wsplit_kernel<<<dim3(3 * D_ / 32, D_ / 32), blk>>>(
                qkvw + (size_t)l * D_ * 3 * D_, wq + (size_t)l * 3 * D_ * D_, D_, 3 * D_);
            wsplit_kernel<<<dim3(D_ / 32, D_ / 32), blk>>>(
                projw + (size_t)l * D_ * D_, wp + (size_t)l * D_ * D_, D_, D_);
            wsplit_kernel<<<dim3(F_ / 32, D_ / 32), blk>>>(
                fc1w + (size_t)l * D_ * F_, w1 + (size_t)l * F_ * D_, D_, F_);
            wsplit_kernel<<<dim3(D_ / 32, F_ / 32), blk>>>(
                fc2w + (size_t)l * F_ * D_, w2 + (size_t)l * D_ * F_, F_, D_);
        }
        split_kernel<<<1024, 256>>>(conv_w, cw16, D_ * D_);
    }

    // ---- patch embed (tensor core) ----
    extract_patches_kernel<<<2048, 256>>>(x, p16);
    gemm_mma_kernel<<<dim3(D_ / 128, (PROWS + 127) / 128), 256, GSMEM_SZ>>>(
        p16, cw16, conv_b, emb, nullptr, nullptr, PROWS, D_, D_, 0);
    assemble_kernel<<<2048, 256>>>(emb, cls_tok, pos, h);

    const int mb = (ROWS + 127) / 128;  // 50
    for (int l = 0; l < L_; l++) {
        ln_h_kernel<<<ROWS, 256>>>(h, ln1w + l * D_, ln1b + l * D_, y16);
        gemm_mma_kernel<<<dim3(3 * D_ / 128, mb), 256, GSMEM_SZ>>>(
            y16, wq + (size_t)l * 3 * D_ * D_, qkvb + (size_t)l * 3 * D_,
            qkv, nullptr, nullptr, ROWS, 3 * D_, D_, 0);
        attn_kernel<<<B_ * H_, 256, ATTN_SMEM>>>(qkv, o16);
        gemm_mma_kernel<<<dim3(D_ / 128, mb), 256, GSMEM_SZ>>>(
            o16, wp + (size_t)l * D_ * D_, projb + (size_t)l * D_,
            nullptr, h, nullptr, ROWS, D_, D_, 1);
        ln_h_kernel<<<ROWS, 256>>>(h, ln2w + l * D_, ln2b + l * D_, y16);
        gemm_mma_kernel<<<dim3(F_ / 128, mb), 256, GSMEM_SZ>>>(
            y16, w1 + (size_t)l * F_ * D_, fc1b + (size_t)l * F_,
            nullptr, nullptr, mid16, ROWS, F_, D_, 2);
        gemm_mma_kernel<<<dim3(D_ / 128, mb), 256, GSMEM_SZ>>>(
            mid16, w2 + (size_t)l * D_ * F_, fc2b + (size_t)l * D_,
            nullptr, h, nullptr, ROWS, D_, F_, 1);
    }

    ln_kernel<<<B_, 256>>>(h, lnfw, lnfb, (float*)d_out, D_, NTOK * D_, D_);
}

// round 7
// speedup vs baseline: 6.0753x; 1.5419x over previous
#include <cuda_runtime.h>
#include <cuda_fp16.h>
#include <math.h>
#include <stdint.h>

#define B_  32
#define NTOK 197
#define NPATCH 196
#define D_  768
#define H_  12
#define DH  64
#define F_  3072
#define L_  12
#define ROWS  (B_*NTOK)    /* 6304 */
#define PROWS (B_*NPATCH)  /* 6272 */

typedef __half h16;

// single dynamic-shared symbol for the whole TU
extern __shared__ char dynsmem[];

// ---------------- scratch (device globals; no allocation) ----------------
__device__ float g_emb[PROWS * D_];
__device__ float g_h[ROWS * D_];
__device__ float g_qkv[ROWS * 3 * D_];

__device__ h16 g_p16[PROWS * D_];
__device__ h16 g_cw16[D_ * D_];

__device__ h16 g_y16[ROWS * D_];
__device__ h16 g_o16[ROWS * D_];
__device__ h16 g_mid16[ROWS * F_];

// transposed weights: stored [N][K] per layer
__device__ h16 g_wqkv[L_ * 3 * D_ * D_];
__device__ h16 g_wproj[L_ * D_ * D_];
__device__ h16 g_wfc1[L_ * F_ * D_];
__device__ h16 g_wfc2[L_ * D_ * F_];

// ---------------- helpers ----------------
__device__ __forceinline__ uint32_t smem_u32(const void* p) {
    uint32_t a;
    asm("{ .reg .u64 t; cvta.to.shared.u64 t, %1; cvt.u32.u64 %0, t; }" : "=r"(a) : "l"(p));
    return a;
}
#define SW128(off) ((off) ^ (((off) >> 3) & 0x70))

#define LDSM_X4(r0, r1, r2, r3, addr) \
    asm volatile("ldmatrix.sync.aligned.m8n8.x4.shared.b16 {%0,%1,%2,%3}, [%4];" \
        : "=r"(r0), "=r"(r1), "=r"(r2), "=r"(r3) : "r"(addr))

#define MMA16816(d, a, b0, b1) \
    asm volatile("mma.sync.aligned.m16n8k16.row.col.f32.f16.f16.f32 " \
        "{%0,%1,%2,%3}, {%4,%5,%6,%7}, {%8,%9}, {%0,%1,%2,%3};" \
        : "+f"((d)[0]), "+f"((d)[1]), "+f"((d)[2]), "+f"((d)[3]) \
        : "r"((a)[0]), "r"((a)[1]), "r"((a)[2]), "r"((a)[3]), "r"(b0), "r"(b1))

#define CP_ASYNC16(dst, src, sz) \
    asm volatile("cp.async.cg.shared.global [%0], [%1], 16, %2;" \
        :: "r"(dst), "l"(src), "r"(sz) : "memory")

// ---------------- tensor-core GEMM via mma.sync (fp16 in, fp32 accum) ----------------
// C[M,N] = A[M,K] @ B[N,K]^T + bias, modes:
//   0 = outf[row*N+col] = v
//   1 = hres[row*N+col] += v  (residual)
//   2 = gelu(v) -> o16 fp16
#define GSTAGE 32768
#define GSMEM_SZ (2 * GSTAGE + 1024)

__global__ void __launch_bounds__(256, 2) gemm_mma_kernel(
    const h16* __restrict__ A, const h16* __restrict__ Bw,
    const float* __restrict__ bias,
    float* __restrict__ outf, float* __restrict__ hres,
    h16* __restrict__ o16,
    int M, int N, int K, int mode)
{
    const uint32_t sbase = (smem_u32(dynsmem) + 1023) & ~1023u;
    const int tid = threadIdx.x;
    const int bm = blockIdx.y * 128;
    const int bn = blockIdx.x * 128;
    const int NC = K >> 6;
    const int w = tid >> 5, lane = tid & 31;
    const int wm = w & 3, wn = w >> 2;

    float acc[2][8][4];
#pragma unroll
    for (int mt = 0; mt < 2; mt++)
#pragma unroll
        for (int nt = 0; nt < 8; nt++)
#pragma unroll
            for (int r = 0; r < 4; r++) acc[mt][nt][r] = 0.f;

    auto load_stage = [&](int c) {
        const uint32_t sb = sbase + (uint32_t)(c & 1) * GSTAGE;
        const int k0 = c * 64;
#pragma unroll
        for (int t = 0; t < 2; t++) {
#pragma unroll
            for (int i = 0; i < 4; i++) {
                int s = tid + i * 256;
                int r = s >> 3, seg = s & 7;
                int grow = (t == 0) ? (bm + r) : (bn + r);
                int sz = 16;
                if (t == 0 && grow >= M) { grow = 0; sz = 0; }
                const h16* src = (t == 0 ? A : Bw) + (size_t)grow * K + k0 + seg * 8;
                uint32_t dst = sb + t * 16384 + SW128((uint32_t)(r * 128 + seg * 16));
                CP_ASYNC16(dst, src, sz);
            }
        }
        asm volatile("cp.async.commit_group;" ::: "memory");
    };

    load_stage(0);

    for (int c = 0; c < NC; c++) {
        if (c + 1 < NC) {
            load_stage(c + 1);
            asm volatile("cp.async.wait_group 1;" ::: "memory");
        } else {
            asm volatile("cp.async.wait_group 0;" ::: "memory");
        }
        __syncthreads();

        const uint32_t sb = sbase + (uint32_t)(c & 1) * GSTAGE;
        const uint32_t sa = sb, sbw = sb + 16384;

#pragma unroll
        for (int k16 = 0; k16 < 4; k16++) {
            const int kc = k16 * 16;
            uint32_t Af[2][4];
#pragma unroll
            for (int mt = 0; mt < 2; mt++) {
                uint32_t aoff = SW128((uint32_t)((wm * 32 + mt * 16 + (lane & 15)) * 128
                                                 + (kc + (lane >> 4) * 8) * 2));
                LDSM_X4(Af[mt][0], Af[mt][1], Af[mt][2], Af[mt][3], sa + aoff);
            }
            const int sub = lane >> 3, r8 = lane & 7;
            const int nloc = ((sub & 2) ? 8 : 0) + r8;
            const int kloc = kc + (sub & 1) * 8;
#pragma unroll
            for (int ng = 0; ng < 4; ng++) {
                uint32_t boff = SW128((uint32_t)((wn * 64 + ng * 16 + nloc) * 128 + kloc * 2));
                uint32_t Bf[4];
                LDSM_X4(Bf[0], Bf[1], Bf[2], Bf[3], sbw + boff);
#pragma unroll
                for (int mt = 0; mt < 2; mt++) {
#pragma unroll
                    for (int half = 0; half < 2; half++) {
                        const int nt = ng * 2 + half;
                        MMA16816(acc[mt][nt], Af[mt], Bf[half * 2], Bf[half * 2 + 1]);
                    }
                }
            }
        }
        __syncthreads();
    }

    // ---- epilogue ----
#pragma unroll
    for (int mt = 0; mt < 2; mt++) {
        const int r0 = bm + wm * 32 + mt * 16 + (lane >> 2);
#pragma unroll
        for (int nt = 0; nt < 8; nt++) {
            const int col = bn + wn * 64 + nt * 8 + (lane & 3) * 2;
            const float b0 = bias[col], b1 = bias[col + 1];
#pragma unroll
            for (int rr = 0; rr < 2; rr++) {
                const int row = r0 + rr * 8;
                if (row >= M) continue;
                float v0 = acc[mt][nt][rr * 2 + 0] + b0;
                float v1 = acc[mt][nt][rr * 2 + 1] + b1;
                size_t oi = (size_t)row * N + col;
                if (mode == 0) {
                    outf[oi] = v0; outf[oi + 1] = v1;
                } else if (mode == 1) {
                    hres[oi] += v0; hres[oi + 1] += v1;
                } else {
                    float g0 = 0.5f * v0 * (1.0f + erff(v0 * 0.70710678118654752f));
                    float g1 = 0.5f * v1 * (1.0f + erff(v1 * 0.70710678118654752f));
                    o16[oi] = __float2half(g0);
                    o16[oi + 1] = __float2half(g1);
                }
            }
        }
    }
}

// ---------------- batched weight transpose + fp16: W[K,N] -> WT [N,K], per layer z ----------------
__global__ void wsplit_all_kernel(const float* __restrict__ W, h16* __restrict__ WT,
                                  int K, int N) {
    __shared__ float t[32][33];
    const size_t off = (size_t)blockIdx.z * K * N;
    const float* Wl = W + off;
    h16* WTl = WT + off;
    int n0 = blockIdx.x * 32, k0 = blockIdx.y * 32;
    int tx = threadIdx.x, ty = threadIdx.y;  // 32 x 8
#pragma unroll
    for (int j = 0; j < 4; j++)
        t[ty + 8 * j][tx] = Wl[(size_t)(k0 + ty + 8 * j) * N + n0 + tx];
    __syncthreads();
#pragma unroll
    for (int j = 0; j < 4; j++) {
        int n = n0 + ty + 8 * j, k = k0 + tx;
        WTl[(size_t)n * K + k] = __float2half(t[tx][ty + 8 * j]);
    }
}

// plain convert (already [N][K]): conv_w
__global__ void split_kernel(const float* __restrict__ W, h16* __restrict__ o, int total) {
    for (int i = blockIdx.x * blockDim.x + threadIdx.x; i < total; i += gridDim.x * blockDim.x)
        o[i] = __float2half(W[i]);
}

// ---------------- patch extraction (fp16) ----------------
__global__ void extract_patches_kernel(const float* __restrict__ x, h16* __restrict__ p16) {
    const int total = PROWS * D_;
    for (int idx = blockIdx.x * blockDim.x + threadIdx.x; idx < total; idx += gridDim.x * blockDim.x) {
        int row = idx / D_;
        int k   = idx % D_;
        int b   = row / NPATCH;
        int t   = row % NPATCH;
        int ph  = t / 14, pw = t % 14;
        int cin = k / 256;
        int rem = k % 256;
        int py  = rem / 16, px = rem % 16;
        size_t src = (((size_t)b * 3 + cin) * 224 + (ph * 16 + py)) * 224 + (pw * 16 + px);
        p16[idx] = __float2half(x[src]);
    }
}

__global__ void assemble_kernel(const float* __restrict__ emb, const float* __restrict__ cls,
                                const float* __restrict__ pos, float* __restrict__ h) {
    const int total = ROWS * D_;
    for (int idx = blockIdx.x * blockDim.x + threadIdx.x; idx < total; idx += gridDim.x * blockDim.x) {
        int r = idx / D_, d = idx % D_;
        int t = r % NTOK;
        int b = r / NTOK;
        float v = pos[t * D_ + d];
        if (t == 0) v += cls[d];
        else        v += emb[((size_t)b * NPATCH + (t - 1)) * D_ + d];
        h[idx] = v;
    }
}

// ---------------- LayerNorm (fp32 out, for final 32 rows) ----------------
__global__ void ln_kernel(const float* __restrict__ x, const float* __restrict__ w,
                          const float* __restrict__ b, float* __restrict__ y,
                          int D, int inStride, int outStride) {
    const int row = blockIdx.x;
    const float* xr = x + (size_t)row * inStride;
    float* yr = y + (size_t)row * outStride;
    const int tid = threadIdx.x;
    float s = 0.f, q = 0.f;
    for (int i = tid; i < D; i += blockDim.x) { float v = xr[i]; s += v; q += v * v; }
    for (int o = 16; o; o >>= 1) { s += __shfl_xor_sync(~0u, s, o); q += __shfl_xor_sync(~0u, q, o); }
    __shared__ float ss[8], sq[8], mean_s, rstd_s;
    int wid = tid >> 5, lane = tid & 31;
    if (lane == 0) { ss[wid] = s; sq[wid] = q; }
    __syncthreads();
    if (tid == 0) {
        float ts = 0.f, tq = 0.f;
        for (int i = 0; i < (int)(blockDim.x >> 5); i++) { ts += ss[i]; tq += sq[i]; }
        float m = ts / D;
        mean_s = m;
        rstd_s = rsqrtf(tq / D - m * m + 1e-6f);
    }
    __syncthreads();
    float m = mean_s, rs = rstd_s;
    for (int i = tid; i < D; i += blockDim.x)
        yr[i] = (xr[i] - m) * rs * w[i] + b[i];
}

// ---------------- warp-per-row LayerNorm -> fp16 (D=768) ----------------
__global__ void __launch_bounds__(256) ln_h_warp_kernel(
    const float* __restrict__ x, const float* __restrict__ wv,
    const float* __restrict__ bv, h16* __restrict__ y16, int rows)
{
    const int row = blockIdx.x * 8 + (threadIdx.x >> 5);
    if (row >= rows) return;
    const int lane = threadIdx.x & 31;
    const float4* xr = (const float4*)(x + (size_t)row * D_);
    float4 vals[6];
    float s = 0.f, q = 0.f;
#pragma unroll
    for (int k = 0; k < 6; k++) {
        float4 v = xr[lane + 32 * k];
        vals[k] = v;
        s += v.x + v.y + v.z + v.w;
        q += v.x * v.x + v.y * v.y + v.z * v.z + v.w * v.w;
    }
#pragma unroll
    for (int o = 16; o; o >>= 1) {
        s += __shfl_xor_sync(~0u, s, o);
        q += __shfl_xor_sync(~0u, q, o);
    }
    const float m = s / D_;
    const float rs = rsqrtf(q / D_ - m * m + 1e-6f);
    uint2* yo = (uint2*)(y16 + (size_t)row * D_);
    const float4* w4 = (const float4*)wv;
    const float4* b4 = (const float4*)bv;
#pragma unroll
    for (int k = 0; k < 6; k++) {
        float4 v = vals[k];
        float4 ww = w4[lane + 32 * k];
        float4 bb = b4[lane + 32 * k];
        __half2 lo = __floats2half2_rn((v.x - m) * rs * ww.x + bb.x,
                                       (v.y - m) * rs * ww.y + bb.y);
        __half2 hi = __floats2half2_rn((v.z - m) * rs * ww.z + bb.z,
                                       (v.w - m) * rs * ww.w + bb.w);
        uint2 u;
        u.x = *(uint32_t*)&lo;
        u.y = *(uint32_t*)&hi;
        yo[lane + 32 * k] = u;
    }
}

// ---------------- fused attention v2: register-tiled fp32, fp16 output ----------------
// smem: Qs[197*65], Ks[197*65], Vs[197*65], Ps[8 warps][8*200]
#define AT_S 65
#define ATTN_SMEM ((3 * NTOK * AT_S + 8 * 8 * 200) * (int)sizeof(float))
__global__ void __launch_bounds__(256, 1) attn_kernel(const float* __restrict__ qkv,
                                                      h16* __restrict__ o16) {
    float* smem = (float*)dynsmem;
    float* Qs = smem;
    float* Ks = Qs + NTOK * AT_S;
    float* Vs = Ks + NTOK * AT_S;
    float* Ps = Vs + NTOK * AT_S;

    const int bh = blockIdx.x;
    const int b = bh / H_;
    const int h = bh % H_;
    const int tid = threadIdx.x;
    const int lane = tid & 31;
    const int w = tid >> 5;

    for (int idx = tid; idx < NTOK * DH; idx += 256) {
        int m = idx >> 6, d = idx & 63;
        size_t base = ((size_t)(b * NTOK + m)) * (3 * D_) + h * DH + d;
        Qs[m * AT_S + d] = qkv[base];
        Ks[m * AT_S + d] = qkv[base + D_];
        Vs[m * AT_S + d] = qkv[base + 2 * D_];
    }
    __syncthreads();

    float* Pw = Ps + w * 8 * 200;

    // key indices this lane covers (clamped; validity masked later)
    int mj[7];
    bool mv[7];
#pragma unroll
    for (int j = 0; j < 7; j++) {
        int m = lane + 32 * j;
        mv[j] = (m < NTOK);
        mj[j] = mv[j] ? m : (NTOK - 1);
    }

    for (int g = w; g < 25; g += 8) {
        const int r0 = g * 8;
        const int nr = (NTOK - r0 < 8) ? (NTOK - r0) : 8;

        // ---- S = Q K^T for 8 query rows ----
        float acc[8][7];
#pragma unroll
        for (int r = 0; r < 8; r++)
#pragma unroll
            for (int j = 0; j < 7; j++) acc[r][j] = 0.f;

        // clamped row indices (avoid OOB smem reads on last group)
        int rr_[8];
#pragma unroll
        for (int r = 0; r < 8; r++) {
            int rr = r0 + r;
            rr_[r] = (rr < NTOK) ? rr : (NTOK - 1);
        }

        for (int d = 0; d < DH; d++) {
            float qv[8];
#pragma unroll
            for (int r = 0; r < 8; r++) qv[r] = Qs[rr_[r] * AT_S + d];
#pragma unroll
            for (int j = 0; j < 7; j++) {
                float kv = Ks[mj[j] * AT_S + d];
#pragma unroll
                for (int r = 0; r < 8; r++) acc[r][j] += qv[r] * kv;
            }
        }

        // ---- softmax per row, P written to smem ----
#pragma unroll
        for (int r = 0; r < 8; r++) {
            float mx = -1e30f;
#pragma unroll
            for (int j = 0; j < 7; j++) {
                float s = mv[j] ? (acc[r][j] * 0.125f) : -1e30f;
                acc[r][j] = s;
                mx = fmaxf(mx, s);
            }
#pragma unroll
            for (int off = 16; off; off >>= 1) mx = fmaxf(mx, __shfl_xor_sync(~0u, mx, off));
            float sum = 0.f;
#pragma unroll
            for (int j = 0; j < 7; j++) {
                if (mv[j]) { acc[r][j] = expf(acc[r][j] - mx); sum += acc[r][j]; }
            }
#pragma unroll
            for (int off = 16; off; off >>= 1) sum += __shfl_xor_sync(~0u, sum, off);
            float inv = 1.f / sum;
#pragma unroll
            for (int j = 0; j < 7; j++)
                if (mv[j]) Pw[r * 200 + lane + 32 * j] = acc[r][j] * inv;
        }
        __syncwarp();

        // ---- O = P V for the 8 rows; lane covers cols lane, lane+32 ----
        float o0[8], o1[8];
#pragma unroll
        for (int r = 0; r < 8; r++) { o0[r] = 0.f; o1[r] = 0.f; }
#pragma unroll 4
        for (int m = 0; m < NTOK; m++) {
            float v0 = Vs[m * AT_S + lane];
            float v1 = Vs[m * AT_S + lane + 32];
#pragma unroll
            for (int r = 0; r < 8; r++) {
                float p = Pw[r * 200 + m];
                o0[r] += p * v0;
                o1[r] += p * v1;
            }
        }
#pragma unroll
        for (int r = 0; r < 8; r++) {
            if (r < nr) {
                size_t obase = ((size_t)(b * NTOK + r0 + r)) * D_ + h * DH;
                o16[obase + lane]      = __float2half(o0[r]);
                o16[obase + lane + 32] = __float2half(o1[r]);
            }
        }
        __syncwarp();
    }
}

// ---------------- host ----------------
extern "C" void kernel_launch(void* const* d_in, const int* in_sizes, int n_in,
                              void* d_out, int out_size) {
    const float* x       = (const float*)d_in[0];
    const float* conv_w  = (const float*)d_in[1];
    const float* conv_b  = (const float*)d_in[2];
    const float* cls_tok = (const float*)d_in[3];
    const float* pos     = (const float*)d_in[4];
    const float* ln1w    = (const float*)d_in[5];
    const float* ln1b    = (const float*)d_in[6];
    const float* qkvw    = (const float*)d_in[7];
    const float* qkvb    = (const float*)d_in[8];
    const float* projw   = (const float*)d_in[9];
    const float* projb   = (const float*)d_in[10];
    const float* ln2w    = (const float*)d_in[11];
    const float* ln2b    = (const float*)d_in[12];
    const float* fc1w    = (const float*)d_in[13];
    const float* fc1b    = (const float*)d_in[14];
    const float* fc2w    = (const float*)d_in[15];
    const float* fc2b    = (const float*)d_in[16];
    const float* lnfw    = (const float*)d_in[17];
    const float* lnfb    = (const float*)d_in[18];

    float *emb, *h, *qkv;
    h16 *p16, *cw16, *y16, *o16, *mid16;
    h16 *wq, *wp, *w1, *w2;
    cudaGetSymbolAddress((void**)&emb,   g_emb);
    cudaGetSymbolAddress((void**)&h,     g_h);
    cudaGetSymbolAddress((void**)&qkv,   g_qkv);
    cudaGetSymbolAddress((void**)&p16,   g_p16);
    cudaGetSymbolAddress((void**)&cw16,  g_cw16);
    cudaGetSymbolAddress((void**)&y16,   g_y16);
    cudaGetSymbolAddress((void**)&o16,   g_o16);
    cudaGetSymbolAddress((void**)&mid16, g_mid16);
    cudaGetSymbolAddress((void**)&wq,    g_wqkv);
    cudaGetSymbolAddress((void**)&wp,    g_wproj);
    cudaGetSymbolAddress((void**)&w1,    g_wfc1);
    cudaGetSymbolAddress((void**)&w2,    g_wfc2);

    cudaFuncSetAttribute(attn_kernel, cudaFuncAttributeMaxDynamicSharedMemorySize, ATTN_SMEM);
    cudaFuncSetAttribute(gemm_mma_kernel, cudaFuncAttributeMaxDynamicSharedMemorySize, GSMEM_SZ);

    // ---- weight conversion (transpose + fp16), batched over layers ----
    {
        dim3 blk(32, 8);
        wsplit_all_kernel<<<dim3(3 * D_ / 32, D_ / 32, L_), blk>>>(qkvw, wq, D_, 3 * D_);
        wsplit_all_kernel<<<dim3(D_ / 32, D_ / 32, L_), blk>>>(projw, wp, D_, D_);
        wsplit_all_kernel<<<dim3(F_ / 32, D_ / 32, L_), blk>>>(fc1w, w1, D_, F_);
        wsplit_all_kernel<<<dim3(D_ / 32, F_ / 32, L_), blk>>>(fc2w, w2, F_, D_);
        split_kernel<<<1024, 256>>>(conv_w, cw16, D_ * D_);
    }

    // ---- patch embed (tensor core) ----
    extract_patches_kernel<<<2048, 256>>>(x, p16);
    gemm_mma_kernel<<<dim3(D_ / 128, (PROWS + 127) / 128), 256, GSMEM_SZ>>>(
        p16, cw16, conv_b, emb, nullptr, nullptr, PROWS, D_, D_, 0);
    assemble_kernel<<<2048, 256>>>(emb, cls_tok, pos, h);

    const int mb = (ROWS + 127) / 128;   // 50
    const int lnb = (ROWS + 7) / 8;      // 788
    for (int l = 0; l < L_; l++) {
        ln_h_warp_kernel<<<lnb, 256>>>(h, ln1w + l * D_, ln1b + l * D_, y16, ROWS);
        gemm_mma_kernel<<<dim3(3 * D_ / 128, mb), 256, GSMEM_SZ>>>(
            y16, wq + (size_t)l * 3 * D_ * D_, qkvb + (size_t)l * 3 * D_,
            qkv, nullptr, nullptr, ROWS, 3 * D_, D_, 0);
        attn_kernel<<<B_ * H_, 256, ATTN_SMEM>>>(qkv, o16);
        gemm_mma_kernel<<<dim3(D_ / 128, mb), 256, GSMEM_SZ>>>(
            o16, wp + (size_t)l * D_ * D_, projb + (size_t)l * D_,
            nullptr, h, nullptr, ROWS, D_, D_, 1);
        ln_h_warp_kernel<<<lnb, 256>>>(h, ln2w + l * D_, ln2b + l * D_, y16, ROWS);
        gemm_mma_kernel<<<dim3(F_ / 128, mb), 256, GSMEM_SZ>>>(
            y16, w1 + (size_t)l * F_ * D_, fc1b + (size_t)l * F_,
            nullptr, nullptr, mid16, ROWS, F_, D_, 2);
        gemm_mma_kernel<<<dim3(D_ / 128, mb), 256, GSMEM_SZ>>>(
            mid16, w2 + (size_t)l * D_ * F_, fc2b + (size_t)l * D_,
            nullptr, h, nullptr, ROWS, D_, F_, 1);
    }

    ln_kernel<<<B_, 256>>>(h, lnfw, lnfb, (float*)d_out, D_, NTOK * D_, D_);
}

// round 8
// speedup vs baseline: 8.1901x; 1.3481x over previous
#include <cuda_runtime.h>
#include <cuda_fp16.h>
#include <math.h>
#include <stdint.h>

#define B_  32
#define NTOK 197
#define NPATCH 196
#define D_  768
#define H_  12
#define DH  64
#define F_  3072
#define L_  12
#define ROWS  (B_*NTOK)    /* 6304 */
#define PROWS (B_*NPATCH)  /* 6272 */

typedef __half h16;

// single dynamic-shared symbol for the whole TU
extern __shared__ char dynsmem[];

// ---------------- scratch (device globals; no allocation) ----------------
__device__ float g_emb[PROWS * D_];
__device__ float g_h[ROWS * D_];
__device__ float g_qkv[ROWS * 3 * D_];

__device__ h16 g_p16[PROWS * D_];
__device__ h16 g_cw16[D_ * D_];

__device__ h16 g_y16[ROWS * D_];
__device__ h16 g_o16[ROWS * D_];
__device__ h16 g_mid16[ROWS * F_];

// transposed weights: stored [N][K] per layer
__device__ h16 g_wqkv[L_ * 3 * D_ * D_];
__device__ h16 g_wproj[L_ * D_ * D_];
__device__ h16 g_wfc1[L_ * F_ * D_];
__device__ h16 g_wfc2[L_ * D_ * F_];

// ---------------- helpers ----------------
__device__ __forceinline__ uint32_t smem_u32(const void* p) {
    uint32_t a;
    asm("{ .reg .u64 t; cvta.to.shared.u64 t, %1; cvt.u32.u64 %0, t; }" : "=r"(a) : "l"(p));
    return a;
}
#define SW128(off) ((off) ^ (((off) >> 3) & 0x70))

#define LDSM_X4(r0, r1, r2, r3, addr) \
    asm volatile("ldmatrix.sync.aligned.m8n8.x4.shared.b16 {%0,%1,%2,%3}, [%4];" \
        : "=r"(r0), "=r"(r1), "=r"(r2), "=r"(r3) : "r"(addr))

#define LDSM_X4_T(r0, r1, r2, r3, addr) \
    asm volatile("ldmatrix.sync.aligned.m8n8.x4.trans.shared.b16 {%0,%1,%2,%3}, [%4];" \
        : "=r"(r0), "=r"(r1), "=r"(r2), "=r"(r3) : "r"(addr))

#define MMA16816(d, a, b0, b1) \
    asm volatile("mma.sync.aligned.m16n8k16.row.col.f32.f16.f16.f32 " \
        "{%0,%1,%2,%3}, {%4,%5,%6,%7}, {%8,%9}, {%0,%1,%2,%3};" \
        : "+f"((d)[0]), "+f"((d)[1]), "+f"((d)[2]), "+f"((d)[3]) \
        : "r"((a)[0]), "r"((a)[1]), "r"((a)[2]), "r"((a)[3]), "r"(b0), "r"(b1))

#define CP_ASYNC16(dst, src, sz) \
    asm volatile("cp.async.cg.shared.global [%0], [%1], 16, %2;" \
        :: "r"(dst), "l"(src), "r"(sz) : "memory")

__device__ __forceinline__ uint32_t pack_h2(h16 a, h16 b) {
    __half2 t = __halves2half2(a, b);
    return *(uint32_t*)&t;
}

// ---------------- tensor-core GEMM via mma.sync (fp16 in, fp32 accum) ----------------
#define GSTAGE 32768
#define GSMEM_SZ (2 * GSTAGE + 1024)

__global__ void __launch_bounds__(256, 2) gemm_mma_kernel(
    const h16* __restrict__ A, const h16* __restrict__ Bw,
    const float* __restrict__ bias,
    float* __restrict__ outf, float* __restrict__ hres,
    h16* __restrict__ o16,
    int M, int N, int K, int mode)
{
    const uint32_t sbase = (smem_u32(dynsmem) + 1023) & ~1023u;
    const int tid = threadIdx.x;
    const int bm = blockIdx.y * 128;
    const int bn = blockIdx.x * 128;
    const int NC = K >> 6;
    const int w = tid >> 5, lane = tid & 31;
    const int wm = w & 3, wn = w >> 2;

    float acc[2][8][4];
#pragma unroll
    for (int mt = 0; mt < 2; mt++)
#pragma unroll
        for (int nt = 0; nt < 8; nt++)
#pragma unroll
            for (int r = 0; r < 4; r++) acc[mt][nt][r] = 0.f;

    auto load_stage = [&](int c) {
        const uint32_t sb = sbase + (uint32_t)(c & 1) * GSTAGE;
        const int k0 = c * 64;
#pragma unroll
        for (int t = 0; t < 2; t++) {
#pragma unroll
            for (int i = 0; i < 4; i++) {
                int s = tid + i * 256;
                int r = s >> 3, seg = s & 7;
                int grow = (t == 0) ? (bm + r) : (bn + r);
                int sz = 16;
                if (t == 0 && grow >= M) { grow = 0; sz = 0; }
                const h16* src = (t == 0 ? A : Bw) + (size_t)grow * K + k0 + seg * 8;
                uint32_t dst = sb + t * 16384 + SW128((uint32_t)(r * 128 + seg * 16));
                CP_ASYNC16(dst, src, sz);
            }
        }
        asm volatile("cp.async.commit_group;" ::: "memory");
    };

    load_stage(0);

    for (int c = 0; c < NC; c++) {
        if (c + 1 < NC) {
            load_stage(c + 1);
            asm volatile("cp.async.wait_group 1;" ::: "memory");
        } else {
            asm volatile("cp.async.wait_group 0;" ::: "memory");
        }
        __syncthreads();

        const uint32_t sb = sbase + (uint32_t)(c & 1) * GSTAGE;
        const uint32_t sa = sb, sbw = sb + 16384;

#pragma unroll
        for (int k16 = 0; k16 < 4; k16++) {
            const int kc = k16 * 16;
            uint32_t Af[2][4];
#pragma unroll
            for (int mt = 0; mt < 2; mt++) {
                uint32_t aoff = SW128((uint32_t)((wm * 32 + mt * 16 + (lane & 15)) * 128
                                                 + (kc + (lane >> 4) * 8) * 2));
                LDSM_X4(Af[mt][0], Af[mt][1], Af[mt][2], Af[mt][3], sa + aoff);
            }
            const int sub = lane >> 3, r8 = lane & 7;
            const int nloc = ((sub & 2) ? 8 : 0) + r8;
            const int kloc = kc + (sub & 1) * 8;
#pragma unroll
            for (int ng = 0; ng < 4; ng++) {
                uint32_t boff = SW128((uint32_t)((wn * 64 + ng * 16 + nloc) * 128 + kloc * 2));
                uint32_t Bf[4];
                LDSM_X4(Bf[0], Bf[1], Bf[2], Bf[3], sbw + boff);
#pragma unroll
                for (int mt = 0; mt < 2; mt++) {
#pragma unroll
                    for (int half = 0; half < 2; half++) {
                        const int nt = ng * 2 + half;
                        MMA16816(acc[mt][nt], Af[mt], Bf[half * 2], Bf[half * 2 + 1]);
                    }
                }
            }
        }
        __syncthreads();
    }

    // ---- epilogue ----
#pragma unroll
    for (int mt = 0; mt < 2; mt++) {
        const int r0 = bm + wm * 32 + mt * 16 + (lane >> 2);
#pragma unroll
        for (int nt = 0; nt < 8; nt++) {
            const int col = bn + wn * 64 + nt * 8 + (lane & 3) * 2;
            const float b0 = bias[col], b1 = bias[col + 1];
#pragma unroll
            for (int rr = 0; rr < 2; rr++) {
                const int row = r0 + rr * 8;
                if (row >= M) continue;
                float v0 = acc[mt][nt][rr * 2 + 0] + b0;
                float v1 = acc[mt][nt][rr * 2 + 1] + b1;
                size_t oi = (size_t)row * N + col;
                if (mode == 0) {
                    outf[oi] = v0; outf[oi + 1] = v1;
                } else if (mode == 1) {
                    hres[oi] += v0; hres[oi + 1] += v1;
                } else {
                    float g0 = 0.5f * v0 * (1.0f + erff(v0 * 0.70710678118654752f));
                    float g1 = 0.5f * v1 * (1.0f + erff(v1 * 0.70710678118654752f));
                    o16[oi] = __float2half(g0);
                    o16[oi + 1] = __float2half(g1);
                }
            }
        }
    }
}

// ---------------- batched weight transpose + fp16 ----------------
__global__ void wsplit_all_kernel(const float* __restrict__ W, h16* __restrict__ WT,
                                  int K, int N) {
    __shared__ float t[32][33];
    const size_t off = (size_t)blockIdx.z * K * N;
    const float* Wl = W + off;
    h16* WTl = WT + off;
    int n0 = blockIdx.x * 32, k0 = blockIdx.y * 32;
    int tx = threadIdx.x, ty = threadIdx.y;  // 32 x 8
#pragma unroll
    for (int j = 0; j < 4; j++)
        t[ty + 8 * j][tx] = Wl[(size_t)(k0 + ty + 8 * j) * N + n0 + tx];
    __syncthreads();
#pragma unroll
    for (int j = 0; j < 4; j++) {
        int n = n0 + ty + 8 * j, k = k0 + tx;
        WTl[(size_t)n * K + k] = __float2half(t[tx][ty + 8 * j]);
    }
}

__global__ void split_kernel(const float* __restrict__ W, h16* __restrict__ o, int total) {
    for (int i = blockIdx.x * blockDim.x + threadIdx.x; i < total; i += gridDim.x * blockDim.x)
        o[i] = __float2half(W[i]);
}

// ---------------- patch extraction (fp16) ----------------
__global__ void extract_patches_kernel(const float* __restrict__ x, h16* __restrict__ p16) {
    const int total = PROWS * D_;
    for (int idx = blockIdx.x * blockDim.x + threadIdx.x; idx < total; idx += gridDim.x * blockDim.x) {
        int row = idx / D_;
        int k   = idx % D_;
        int b   = row / NPATCH;
        int t   = row % NPATCH;
        int ph  = t / 14, pw = t % 14;
        int cin = k / 256;
        int rem = k % 256;
        int py  = rem / 16, px = rem % 16;
        size_t src = (((size_t)b * 3 + cin) * 224 + (ph * 16 + py)) * 224 + (pw * 16 + px);
        p16[idx] = __float2half(x[src]);
    }
}

__global__ void assemble_kernel(const float* __restrict__ emb, const float* __restrict__ cls,
                                const float* __restrict__ pos, float* __restrict__ h) {
    const int total = ROWS * D_;
    for (int idx = blockIdx.x * blockDim.x + threadIdx.x; idx < total; idx += gridDim.x * blockDim.x) {
        int r = idx / D_, d = idx % D_;
        int t = r % NTOK;
        int b = r / NTOK;
        float v = pos[t * D_ + d];
        if (t == 0) v += cls[d];
        else        v += emb[((size_t)b * NPATCH + (t - 1)) * D_ + d];
        h[idx] = v;
    }
}

// ---------------- LayerNorm (fp32 out, final rows) ----------------
__global__ void ln_kernel(const float* __restrict__ x, const float* __restrict__ w,
                          const float* __restrict__ b, float* __restrict__ y,
                          int D, int inStride, int outStride) {
    const int row = blockIdx.x;
    const float* xr = x + (size_t)row * inStride;
    float* yr = y + (size_t)row * outStride;
    const int tid = threadIdx.x;
    float s = 0.f, q = 0.f;
    for (int i = tid; i < D; i += blockDim.x) { float v = xr[i]; s += v; q += v * v; }
    for (int o = 16; o; o >>= 1) { s += __shfl_xor_sync(~0u, s, o); q += __shfl_xor_sync(~0u, q, o); }
    __shared__ float ss[8], sq[8], mean_s, rstd_s;
    int wid = tid >> 5, lane = tid & 31;
    if (lane == 0) { ss[wid] = s; sq[wid] = q; }
    __syncthreads();
    if (tid == 0) {
        float ts = 0.f, tq = 0.f;
        for (int i = 0; i < (int)(blockDim.x >> 5); i++) { ts += ss[i]; tq += sq[i]; }
        float m = ts / D;
        mean_s = m;
        rstd_s = rsqrtf(tq / D - m * m + 1e-6f);
    }
    __syncthreads();
    float m = mean_s, rs = rstd_s;
    for (int i = tid; i < D; i += blockDim.x)
        yr[i] = (xr[i] - m) * rs * w[i] + b[i];
}

// ---------------- warp-per-row LayerNorm -> fp16 (D=768) ----------------
__global__ void __launch_bounds__(256) ln_h_warp_kernel(
    const float* __restrict__ x, const float* __restrict__ wv,
    const float* __restrict__ bv, h16* __restrict__ y16, int rows)
{
    const int row = blockIdx.x * 8 + (threadIdx.x >> 5);
    if (row >= rows) return;
    const int lane = threadIdx.x & 31;
    const float4* xr = (const float4*)(x + (size_t)row * D_);
    float4 vals[6];
    float s = 0.f, q = 0.f;
#pragma unroll
    for (int k = 0; k < 6; k++) {
        float4 v = xr[lane + 32 * k];
        vals[k] = v;
        s += v.x + v.y + v.z + v.w;
        q += v.x * v.x + v.y * v.y + v.z * v.z + v.w * v.w;
    }
#pragma unroll
    for (int o = 16; o; o >>= 1) {
        s += __shfl_xor_sync(~0u, s, o);
        q += __shfl_xor_sync(~0u, q, o);
    }
    const float m = s / D_;
    const float rs = rsqrtf(q / D_ - m * m + 1e-6f);
    uint2* yo = (uint2*)(y16 + (size_t)row * D_);
    const float4* w4 = (const float4*)wv;
    const float4* b4 = (const float4*)bv;
#pragma unroll
    for (int k = 0; k < 6; k++) {
        float4 v = vals[k];
        float4 ww = w4[lane + 32 * k];
        float4 bb = b4[lane + 32 * k];
        __half2 lo = __floats2half2_rn((v.x - m) * rs * ww.x + bb.x,
                                       (v.y - m) * rs * ww.y + bb.y);
        __half2 hi = __floats2half2_rn((v.z - m) * rs * ww.z + bb.z,
                                       (v.w - m) * rs * ww.w + bb.w);
        uint2 u;
        u.x = *(uint32_t*)&lo;
        u.y = *(uint32_t*)&hi;
        yo[lane + 32 * k] = u;
    }
}

// ---------------- attention v3: HMMA with 3-product hi/lo splits ----------------
// smem: Qh,Ql,Kh,Kl,Vh,Vl each [208][64] fp16 (128B rows, SW128) = 6*26624 bytes
#define ASLAB 26624
#define AMMA_SMEM (6 * ASLAB)
__global__ void __launch_bounds__(256) attn_kernel(const float* __restrict__ qkv,
                                                   h16* __restrict__ o16) {
    char* sm = dynsmem;
    const uint32_t sbase = smem_u32(sm);
    const uint32_t Qh = sbase,      Ql = Qh + ASLAB;
    const uint32_t Kh = Ql + ASLAB, Kl = Kh + ASLAB;
    const uint32_t Vh = Kl + ASLAB, Vl = Vh + ASLAB;

    const int bh = blockIdx.x;
    const int b = bh / H_;
    const int h = bh % H_;
    const int tid = threadIdx.x;
    const int lane = tid & 31;
    const int w = tid >> 5;

    // ---- stage q,k,v -> hi/lo fp16, SW128, zero-padded to 208 rows ----
    for (int idx = tid; idx < 208 * 32; idx += 256) {
        int m = idx >> 5, dp = idx & 31;     // dp = pair of d
        float2 qv = make_float2(0.f, 0.f), kv = qv, vv = qv;
        if (m < NTOK) {
            const float* base = qkv + ((size_t)(b * NTOK + m)) * (3 * D_) + h * DH + dp * 2;
            qv = *(const float2*)(base);
            kv = *(const float2*)(base + D_);
            vv = *(const float2*)(base + 2 * D_);
        }
        uint32_t off = SW128((uint32_t)(m * 128 + dp * 4));
        h16 a0 = __float2half_rn(qv.x), a1 = __float2half_rn(qv.y);
        *(uint32_t*)(sm + (Qh - sbase) + off) = pack_h2(a0, a1);
        *(uint32_t*)(sm + (Ql - sbase) + off) =
            pack_h2(__float2half_rn(qv.x - __half2float(a0)),
                    __float2half_rn(qv.y - __half2float(a1)));
        h16 k0 = __float2half_rn(kv.x), k1 = __float2half_rn(kv.y);
        *(uint32_t*)(sm + (Kh - sbase) + off) = pack_h2(k0, k1);
        *(uint32_t*)(sm + (Kl - sbase) + off) =
            pack_h2(__float2half_rn(kv.x - __half2float(k0)),
                    __float2half_rn(kv.y - __half2float(k1)));
        h16 v0 = __float2half_rn(vv.x), v1 = __float2half_rn(vv.y);
        *(uint32_t*)(sm + (Vh - sbase) + off) = pack_h2(v0, v1);
        *(uint32_t*)(sm + (Vl - sbase) + off) =
            pack_h2(__float2half_rn(vv.x - __half2float(v0)),
                    __float2half_rn(vv.y - __half2float(v1)));
    }
    __syncthreads();

    const int c0 = (lane & 3) * 2;

    for (int mt = w; mt < 13; mt += 8) {
        // ---- S = Q K^T (3-product) : accS[26 n8-tiles][4] ----
        float accS[26][4];
#pragma unroll
        for (int t = 0; t < 26; t++)
#pragma unroll
            for (int i = 0; i < 4; i++) accS[t][i] = 0.f;

#pragma unroll
        for (int kc = 0; kc < 4; kc++) {
            uint32_t Ah4[4], Al4[4];
            {
                uint32_t aoff = SW128((uint32_t)((mt * 16 + (lane & 15)) * 128
                                                 + (kc * 16 + (lane >> 4) * 8) * 2));
                LDSM_X4(Ah4[0], Ah4[1], Ah4[2], Ah4[3], Qh + aoff);
                LDSM_X4(Al4[0], Al4[1], Al4[2], Al4[3], Ql + aoff);
            }
            const int sub = lane >> 3, r8 = lane & 7;
            const int nloc = ((sub & 2) ? 8 : 0) + r8;
            const int kloc = kc * 16 + (sub & 1) * 8;
#pragma unroll
            for (int np = 0; np < 13; np++) {
                uint32_t boff = SW128((uint32_t)((np * 16 + nloc) * 128 + kloc * 2));
                uint32_t BH[4], BL[4];
                LDSM_X4(BH[0], BH[1], BH[2], BH[3], Kh + boff);
                LDSM_X4(BL[0], BL[1], BL[2], BL[3], Kl + boff);
                MMA16816(accS[2 * np], Ah4, BH[0], BH[1]);
                MMA16816(accS[2 * np], Ah4, BL[0], BL[1]);
                MMA16816(accS[2 * np], Al4, BH[0], BH[1]);
                MMA16816(accS[2 * np + 1], Ah4, BH[2], BH[3]);
                MMA16816(accS[2 * np + 1], Ah4, BL[2], BL[3]);
                MMA16816(accS[2 * np + 1], Al4, BH[2], BH[3]);
            }
        }

        // ---- scale + mask + softmax (fp32) ----
        float mx0 = -1e30f, mx1 = -1e30f;
#pragma unroll
        for (int t = 0; t < 26; t++) {
#pragma unroll
            for (int i = 0; i < 4; i++) {
                int col = t * 8 + c0 + (i & 1);
                float s = (col < NTOK) ? (accS[t][i] * 0.125f) : -1e30f;
                accS[t][i] = s;
                if (i < 2) mx0 = fmaxf(mx0, s);
                else       mx1 = fmaxf(mx1, s);
            }
        }
        mx0 = fmaxf(mx0, __shfl_xor_sync(~0u, mx0, 1));
        mx0 = fmaxf(mx0, __shfl_xor_sync(~0u, mx0, 2));
        mx1 = fmaxf(mx1, __shfl_xor_sync(~0u, mx1, 1));
        mx1 = fmaxf(mx1, __shfl_xor_sync(~0u, mx1, 2));
        float sum0 = 0.f, sum1 = 0.f;
#pragma unroll
        for (int t = 0; t < 26; t++) {
#pragma unroll
            for (int i = 0; i < 4; i++) {
                float e = expf(accS[t][i] - ((i < 2) ? mx0 : mx1));
                accS[t][i] = e;
                if (i < 2) sum0 += e;
                else       sum1 += e;
            }
        }
        sum0 += __shfl_xor_sync(~0u, sum0, 1);
        sum0 += __shfl_xor_sync(~0u, sum0, 2);
        sum1 += __shfl_xor_sync(~0u, sum1, 1);
        sum1 += __shfl_xor_sync(~0u, sum1, 2);
        const float inv0 = 1.f / sum0, inv1 = 1.f / sum1;

        // ---- O = P V (3-product), P fragments built in registers ----
        float accO[8][4];
#pragma unroll
        for (int nt = 0; nt < 8; nt++)
#pragma unroll
            for (int i = 0; i < 4; i++) accO[nt][i] = 0.f;

        const int g = lane >> 3;
        const int vrow_loc = (g & 1) * 8 + (lane & 7);
        const int vcol_b = (g >> 1) * 16;

#pragma unroll
        for (int kk = 0; kk < 13; kk++) {
            float e0 = accS[2 * kk][0] * inv0, e1 = accS[2 * kk][1] * inv0;
            float e2 = accS[2 * kk][2] * inv1, e3 = accS[2 * kk][3] * inv1;
            float f0 = accS[2 * kk + 1][0] * inv0, f1 = accS[2 * kk + 1][1] * inv0;
            float f2 = accS[2 * kk + 1][2] * inv1, f3 = accS[2 * kk + 1][3] * inv1;
            h16 he0 = __float2half_rn(e0), he1 = __float2half_rn(e1);
            h16 he2 = __float2half_rn(e2), he3 = __float2half_rn(e3);
            h16 hf0 = __float2half_rn(f0), hf1 = __float2half_rn(f1);
            h16 hf2 = __float2half_rn(f2), hf3 = __float2half_rn(f3);
            uint32_t aH[4] = { pack_h2(he0, he1), pack_h2(he2, he3),
                               pack_h2(hf0, hf1), pack_h2(hf2, hf3) };
            uint32_t aL[4] = {
                pack_h2(__float2half_rn(e0 - __half2float(he0)), __float2half_rn(e1 - __half2float(he1))),
                pack_h2(__float2half_rn(e2 - __half2float(he2)), __float2half_rn(e3 - __half2float(he3))),
                pack_h2(__float2half_rn(f0 - __half2float(hf0)), __float2half_rn(f1 - __half2float(hf1))),
                pack_h2(__float2half_rn(f2 - __half2float(hf2)), __float2half_rn(f3 - __half2float(hf3))) };

            const int vrow = kk * 16 + vrow_loc;
#pragma unroll
            for (int vg = 0; vg < 4; vg++) {
                uint32_t voff = SW128((uint32_t)(vrow * 128 + vg * 32 + vcol_b));
                uint32_t VH[4], VL[4];
                LDSM_X4_T(VH[0], VH[1], VH[2], VH[3], Vh + voff);
                LDSM_X4_T(VL[0], VL[1], VL[2], VL[3], Vl + voff);
                MMA16816(accO[vg * 2], aH, VH[0], VH[1]);
                MMA16816(accO[vg * 2], aH, VL[0], VL[1]);
                MMA16816(accO[vg * 2], aL, VH[0], VH[1]);
                MMA16816(accO[vg * 2 + 1], aH, VH[2], VH[3]);
                MMA16816(accO[vg * 2 + 1], aH, VL[2], VL[3]);
                MMA16816(accO[vg * 2 + 1], aL, VH[2], VH[3]);
            }
        }

        // ---- store O (fp16) ----
        const int r1 = mt * 16 + (lane >> 2);
        const int r2 = r1 + 8;
#pragma unroll
        for (int nt = 0; nt < 8; nt++) {
            const int col = h * DH + nt * 8 + c0;
            if (r1 < NTOK) {
                __half2 v = __floats2half2_rn(accO[nt][0], accO[nt][1]);
                *(uint32_t*)(o16 + (size_t)(b * NTOK + r1) * D_ + col) = *(uint32_t*)&v;
            }
            if (r2 < NTOK) {
                __half2 v = __floats2half2_rn(accO[nt][2], accO[nt][3]);
                *(uint32_t*)(o16 + (size_t)(b * NTOK + r2) * D_ + col) = *(uint32_t*)&v;
            }
        }
    }
}

// ---------------- host ----------------
extern "C" void kernel_launch(void* const* d_in, const int* in_sizes, int n_in,
                              void* d_out, int out_size) {
    const float* x       = (const float*)d_in[0];
    const float* conv_w  = (const float*)d_in[1];
    const float* conv_b  = (const float*)d_in[2];
    const float* cls_tok = (const float*)d_in[3];
    const float* pos     = (const float*)d_in[4];
    const float* ln1w    = (const float*)d_in[5];
    const float* ln1b    = (const float*)d_in[6];
    const float* qkvw    = (const float*)d_in[7];
    const float* qkvb    = (const float*)d_in[8];
    const float* projw   = (const float*)d_in[9];
    const float* projb   = (const float*)d_in[10];
    const float* ln2w    = (const float*)d_in[11];
    const float* ln2b    = (const float*)d_in[12];
    const float* fc1w    = (const float*)d_in[13];
    const float* fc1b    = (const float*)d_in[14];
    const float* fc2w    = (const float*)d_in[15];
    const float* fc2b    = (const float*)d_in[16];
    const float* lnfw    = (const float*)d_in[17];
    const float* lnfb    = (const float*)d_in[18];

    float *emb, *h, *qkv;
    h16 *p16, *cw16, *y16, *o16, *mid16;
    h16 *wq, *wp, *w1, *w2;
    cudaGetSymbolAddress((void**)&emb,   g_emb);
    cudaGetSymbolAddress((void**)&h,     g_h);
    cudaGetSymbolAddress((void**)&qkv,   g_qkv);
    cudaGetSymbolAddress((void**)&p16,   g_p16);
    cudaGetSymbolAddress((void**)&cw16,  g_cw16);
    cudaGetSymbolAddress((void**)&y16,   g_y16);
    cudaGetSymbolAddress((void**)&o16,   g_o16);
    cudaGetSymbolAddress((void**)&mid16, g_mid16);
    cudaGetSymbolAddress((void**)&wq,    g_wqkv);
    cudaGetSymbolAddress((void**)&wp,    g_wproj);
    cudaGetSymbolAddress((void**)&w1,    g_wfc1);
    cudaGetSymbolAddress((void**)&w2,    g_wfc2);

    cudaFuncSetAttribute(attn_kernel, cudaFuncAttributeMaxDynamicSharedMemorySize, AMMA_SMEM);
    cudaFuncSetAttribute(gemm_mma_kernel, cudaFuncAttributeMaxDynamicSharedMemorySize, GSMEM_SZ);

    // ---- weight conversion (transpose + fp16), batched over layers ----
    {
        dim3 blk(32, 8);
        wsplit_all_kernel<<<dim3(3 * D_ / 32, D_ / 32, L_), blk>>>(qkvw, wq, D_, 3 * D_);
        wsplit_all_kernel<<<dim3(D_ / 32, D_ / 32, L_), blk>>>(projw, wp, D_, D_);
        wsplit_all_kernel<<<dim3(F_ / 32, D_ / 32, L_), blk>>>(fc1w, w1, D_, F_);
        wsplit_all_kernel<<<dim3(D_ / 32, F_ / 32, L_), blk>>>(fc2w, w2, F_, D_);
        split_kernel<<<1024, 256>>>(conv_w, cw16, D_ * D_);
    }

    // ---- patch embed (tensor core) ----
    extract_patches_kernel<<<2048, 256>>>(x, p16);
    gemm_mma_kernel<<<dim3(D_ / 128, (PROWS + 127) / 128), 256, GSMEM_SZ>>>(
        p16, cw16, conv_b, emb, nullptr, nullptr, PROWS, D_, D_, 0);
    assemble_kernel<<<2048, 256>>>(emb, cls_tok, pos, h);

    const int mb = (ROWS + 127) / 128;   // 50
    const int lnb = (ROWS + 7) / 8;      // 788
    for (int l = 0; l < L_; l++) {
        ln_h_warp_kernel<<<lnb, 256>>>(h, ln1w + l * D_, ln1b + l * D_, y16, ROWS);
        gemm_mma_kernel<<<dim3(3 * D_ / 128, mb), 256, GSMEM_SZ>>>(
            y16, wq + (size_t)l * 3 * D_ * D_, qkvb + (size_t)l * 3 * D_,
            qkv, nullptr, nullptr, ROWS, 3 * D_, D_, 0);
        attn_kernel<<<B_ * H_, 256, AMMA_SMEM>>>(qkv, o16);
        gemm_mma_kernel<<<dim3(D_ / 128, mb), 256, GSMEM_SZ>>>(
            o16, wp + (size_t)l * D_ * D_, projb + (size_t)l * D_,
            nullptr, h, nullptr, ROWS, D_, D_, 1);
        ln_h_warp_kernel<<<lnb, 256>>>(h, ln2w + l * D_, ln2b + l * D_, y16, ROWS);
        gemm_mma_kernel<<<dim3(F_ / 128, mb), 256, GSMEM_SZ>>>(
            y16, w1 + (size_t)l * F_ * D_, fc1b + (size_t)l * F_,
            nullptr, nullptr, mid16, ROWS, F_, D_, 2);
        gemm_mma_kernel<<<dim3(D_ / 128, mb), 256, GSMEM_SZ>>>(
            mid16, w2 + (size_t)l * D_ * F_, fc2b + (size_t)l * D_,
            nullptr, h, nullptr, ROWS, D_, F_, 1);
    }

    ln_kernel<<<B_, 256>>>(h, lnfw, lnfb, (float*)d_out, D_, NTOK * D_, D_);
}

// round 9
// speedup vs baseline: 9.1350x; 1.1154x over previous
#include <cuda_runtime.h>
#include <cuda_fp16.h>
#include <math.h>
#include <stdint.h>

#define B_  32
#define NTOK 197
#define NPATCH 196
#define D_  768
#define H_  12
#define DH  64
#define F_  3072
#define L_  12
#define ROWS  (B_*NTOK)    /* 6304 */
#define PROWS (B_*NPATCH)  /* 6272 */

typedef __half h16;

// single dynamic-shared symbol for the whole TU
extern __shared__ char dynsmem[];

// ---------------- scratch (device globals; no allocation) ----------------
__device__ float g_emb[PROWS * D_];
__device__ float g_h[ROWS * D_];
__device__ float g_qkv[ROWS * 3 * D_];

__device__ h16 g_p16[PROWS * D_];
__device__ h16 g_cw16[D_ * D_];

__device__ h16 g_y16[ROWS * D_];
__device__ h16 g_o16[ROWS * D_];
__device__ h16 g_mid16[ROWS * F_];

// transposed weights: stored [N][K] per layer
__device__ h16 g_wqkv[L_ * 3 * D_ * D_];
__device__ h16 g_wproj[L_ * D_ * D_];
__device__ h16 g_wfc1[L_ * F_ * D_];
__device__ h16 g_wfc2[L_ * D_ * F_];

// ---------------- helpers ----------------
__device__ __forceinline__ uint32_t smem_u32(const void* p) {
    uint32_t a;
    asm("{ .reg .u64 t; cvta.to.shared.u64 t, %1; cvt.u32.u64 %0, t; }" : "=r"(a) : "l"(p));
    return a;
}
#define SW128(off) ((off) ^ (((off) >> 3) & 0x70))

#define LDSM_X4(r0, r1, r2, r3, addr) \
    asm volatile("ldmatrix.sync.aligned.m8n8.x4.shared.b16 {%0,%1,%2,%3}, [%4];" \
        : "=r"(r0), "=r"(r1), "=r"(r2), "=r"(r3) : "r"(addr))

#define LDSM_X4_T(r0, r1, r2, r3, addr) \
    asm volatile("ldmatrix.sync.aligned.m8n8.x4.trans.shared.b16 {%0,%1,%2,%3}, [%4];" \
        : "=r"(r0), "=r"(r1), "=r"(r2), "=r"(r3) : "r"(addr))

#define MMA16816(d, a, b0, b1) \
    asm volatile("mma.sync.aligned.m16n8k16.row.col.f32.f16.f16.f32 " \
        "{%0,%1,%2,%3}, {%4,%5,%6,%7}, {%8,%9}, {%0,%1,%2,%3};" \
        : "+f"((d)[0]), "+f"((d)[1]), "+f"((d)[2]), "+f"((d)[3]) \
        : "r"((a)[0]), "r"((a)[1]), "r"((a)[2]), "r"((a)[3]), "r"(b0), "r"(b1))

#define CP_ASYNC16(dst, src, sz) \
    asm volatile("cp.async.cg.shared.global [%0], [%1], 16, %2;" \
        :: "r"(dst), "l"(src), "r"(sz) : "memory")

__device__ __forceinline__ uint32_t pack_h2(h16 a, h16 b) {
    __half2 t = __halves2half2(a, b);
    return *(uint32_t*)&t;
}

// ---------------- tensor-core GEMM via mma.sync (fp16 in, fp32 accum) ----------------
// 3-stage cp.async pipeline, one __syncthreads per K-chunk.
#define GSTAGE 32768
#define GSMEM_SZ (3 * GSTAGE)

__global__ void __launch_bounds__(256, 2) gemm_mma_kernel(
    const h16* __restrict__ A, const h16* __restrict__ Bw,
    const float* __restrict__ bias,
    float* __restrict__ outf, float* __restrict__ hres,
    h16* __restrict__ o16,
    int M, int N, int K, int mode)
{
    const uint32_t sbase = smem_u32(dynsmem);
    const int tid = threadIdx.x;
    const int bm = blockIdx.y * 128;
    const int bn = blockIdx.x * 128;
    const int NC = K >> 6;
    const int w = tid >> 5, lane = tid & 31;
    const int wm = w & 3, wn = w >> 2;

    float acc[2][8][4];
#pragma unroll
    for (int mt = 0; mt < 2; mt++)
#pragma unroll
        for (int nt = 0; nt < 8; nt++)
#pragma unroll
            for (int r = 0; r < 4; r++) acc[mt][nt][r] = 0.f;

    auto load_stage = [&](int c, int slot) {
        const uint32_t sb = sbase + (uint32_t)slot * GSTAGE;
        const int k0 = c * 64;
#pragma unroll
        for (int t = 0; t < 2; t++) {
#pragma unroll
            for (int i = 0; i < 4; i++) {
                int s = tid + i * 256;
                int r = s >> 3, seg = s & 7;
                int grow = (t == 0) ? (bm + r) : (bn + r);
                int sz = 16;
                if (t == 0 && grow >= M) { grow = 0; sz = 0; }
                const h16* src = (t == 0 ? A : Bw) + (size_t)grow * K + k0 + seg * 8;
                uint32_t dst = sb + t * 16384 + SW128((uint32_t)(r * 128 + seg * 16));
                CP_ASYNC16(dst, src, sz);
            }
        }
        asm volatile("cp.async.commit_group;" ::: "memory");
    };

    // prologue: stages 0, 1
    load_stage(0, 0);
    if (NC > 1) load_stage(1, 1);

    int slot = 0;
    for (int c = 0; c < NC; c++) {
        if (c + 1 < NC) {
            asm volatile("cp.async.wait_group 1;" ::: "memory");
        } else {
            asm volatile("cp.async.wait_group 0;" ::: "memory");
        }
        __syncthreads();

        if (c + 2 < NC) {
            int ns = slot + 2;
            if (ns >= 3) ns -= 3;
            load_stage(c + 2, ns);
        }

        const uint32_t sb = sbase + (uint32_t)slot * GSTAGE;
        const uint32_t sa = sb, sbw = sb + 16384;

#pragma unroll
        for (int k16 = 0; k16 < 4; k16++) {
            const int kc = k16 * 16;
            uint32_t Af[2][4];
#pragma unroll
            for (int mt = 0; mt < 2; mt++) {
                uint32_t aoff = SW128((uint32_t)((wm * 32 + mt * 16 + (lane & 15)) * 128
                                                 + (kc + (lane >> 4) * 8) * 2));
                LDSM_X4(Af[mt][0], Af[mt][1], Af[mt][2], Af[mt][3], sa + aoff);
            }
            const int sub = lane >> 3, r8 = lane & 7;
            const int nloc = ((sub & 2) ? 8 : 0) + r8;
            const int kloc = kc + (sub & 1) * 8;
#pragma unroll
            for (int ng = 0; ng < 4; ng++) {
                uint32_t boff = SW128((uint32_t)((wn * 64 + ng * 16 + nloc) * 128 + kloc * 2));
                uint32_t Bf[4];
                LDSM_X4(Bf[0], Bf[1], Bf[2], Bf[3], sbw + boff);
#pragma unroll
                for (int mt = 0; mt < 2; mt++) {
#pragma unroll
                    for (int half = 0; half < 2; half++) {
                        const int nt = ng * 2 + half;
                        MMA16816(acc[mt][nt], Af[mt], Bf[half * 2], Bf[half * 2 + 1]);
                    }
                }
            }
        }

        slot++;
        if (slot >= 3) slot = 0;
    }

    // ---- epilogue ----
#pragma unroll
    for (int mt = 0; mt < 2; mt++) {
        const int r0 = bm + wm * 32 + mt * 16 + (lane >> 2);
#pragma unroll
        for (int nt = 0; nt < 8; nt++) {
            const int col = bn + wn * 64 + nt * 8 + (lane & 3) * 2;
            const float b0 = bias[col], b1 = bias[col + 1];
#pragma unroll
            for (int rr = 0; rr < 2; rr++) {
                const int row = r0 + rr * 8;
                if (row >= M) continue;
                float v0 = acc[mt][nt][rr * 2 + 0] + b0;
                float v1 = acc[mt][nt][rr * 2 + 1] + b1;
                size_t oi = (size_t)row * N + col;
                if (mode == 0) {
                    *(float2*)(outf + oi) = make_float2(v0, v1);
                } else if (mode == 1) {
                    float2* hp = (float2*)(hres + oi);
                    float2 t = *hp;
                    t.x += v0; t.y += v1;
                    *hp = t;
                } else {
                    float g0 = 0.5f * v0 * (1.0f + erff(v0 * 0.70710678118654752f));
                    float g1 = 0.5f * v1 * (1.0f + erff(v1 * 0.70710678118654752f));
                    __half2 hv = __floats2half2_rn(g0, g1);
                    *(uint32_t*)(o16 + oi) = *(uint32_t*)&hv;
                }
            }
        }
    }
}

// ---------------- batched weight transpose + fp16 ----------------
__global__ void wsplit_all_kernel(const float* __restrict__ W, h16* __restrict__ WT,
                                  int K, int N) {
    __shared__ float t[32][33];
    const size_t off = (size_t)blockIdx.z * K * N;
    const float* Wl = W + off;
    h16* WTl = WT + off;
    int n0 = blockIdx.x * 32, k0 = blockIdx.y * 32;
    int tx = threadIdx.x, ty = threadIdx.y;  // 32 x 8
#pragma unroll
    for (int j = 0; j < 4; j++)
        t[ty + 8 * j][tx] = Wl[(size_t)(k0 + ty + 8 * j) * N + n0 + tx];
    __syncthreads();
#pragma unroll
    for (int j = 0; j < 4; j++) {
        int n = n0 + ty + 8 * j, k = k0 + tx;
        WTl[(size_t)n * K + k] = __float2half(t[tx][ty + 8 * j]);
    }
}

__global__ void split_kernel(const float* __restrict__ W, h16* __restrict__ o, int total) {
    for (int i = blockIdx.x * blockDim.x + threadIdx.x; i < total; i += gridDim.x * blockDim.x)
        o[i] = __float2half(W[i]);
}

// ---------------- patch extraction (fp16) ----------------
__global__ void extract_patches_kernel(const float* __restrict__ x, h16* __restrict__ p16) {
    const int total = PROWS * D_;
    for (int idx = blockIdx.x * blockDim.x + threadIdx.x; idx < total; idx += gridDim.x * blockDim.x) {
        int row = idx / D_;
        int k   = idx % D_;
        int b   = row / NPATCH;
        int t   = row % NPATCH;
        int ph  = t / 14, pw = t % 14;
        int cin = k / 256;
        int rem = k % 256;
        int py  = rem / 16, px = rem % 16;
        size_t src = (((size_t)b * 3 + cin) * 224 + (ph * 16 + py)) * 224 + (pw * 16 + px);
        p16[idx] = __float2half(x[src]);
    }
}

__global__ void assemble_kernel(const float* __restrict__ emb, const float* __restrict__ cls,
                                const float* __restrict__ pos, float* __restrict__ h) {
    const int total = ROWS * D_;
    for (int idx = blockIdx.x * blockDim.x + threadIdx.x; idx < total; idx += gridDim.x * blockDim.x) {
        int r = idx / D_, d = idx % D_;
        int t = r % NTOK;
        int b = r / NTOK;
        float v = pos[t * D_ + d];
        if (t == 0) v += cls[d];
        else        v += emb[((size_t)b * NPATCH + (t - 1)) * D_ + d];
        h[idx] = v;
    }
}

// ---------------- LayerNorm (fp32 out, final rows) ----------------
__global__ void ln_kernel(const float* __restrict__ x, const float* __restrict__ w,
                          const float* __restrict__ b, float* __restrict__ y,
                          int D, int inStride, int outStride) {
    const int row = blockIdx.x;
    const float* xr = x + (size_t)row * inStride;
    float* yr = y + (size_t)row * outStride;
    const int tid = threadIdx.x;
    float s = 0.f, q = 0.f;
    for (int i = tid; i < D; i += blockDim.x) { float v = xr[i]; s += v; q += v * v; }
    for (int o = 16; o; o >>= 1) { s += __shfl_xor_sync(~0u, s, o); q += __shfl_xor_sync(~0u, q, o); }
    __shared__ float ss[8], sq[8], mean_s, rstd_s;
    int wid = tid >> 5, lane = tid & 31;
    if (lane == 0) { ss[wid] = s; sq[wid] = q; }
    __syncthreads();
    if (tid == 0) {
        float ts = 0.f, tq = 0.f;
        for (int i = 0; i < (int)(blockDim.x >> 5); i++) { ts += ss[i]; tq += sq[i]; }
        float m = ts / D;
        mean_s = m;
        rstd_s = rsqrtf(tq / D - m * m + 1e-6f);
    }
    __syncthreads();
    float m = mean_s, rs = rstd_s;
    for (int i = tid; i < D; i += blockDim.x)
        yr[i] = (xr[i] - m) * rs * w[i] + b[i];
}

// ---------------- warp-per-row LayerNorm -> fp16 (D=768) ----------------
__global__ void __launch_bounds__(256) ln_h_warp_kernel(
    const float* __restrict__ x, const float* __restrict__ wv,
    const float* __restrict__ bv, h16* __restrict__ y16, int rows)
{
    const int row = blockIdx.x * 8 + (threadIdx.x >> 5);
    if (row >= rows) return;
    const int lane = threadIdx.x & 31;
    const float4* xr = (const float4*)(x + (size_t)row * D_);
    float4 vals[6];
    float s = 0.f, q = 0.f;
#pragma unroll
    for (int k = 0; k < 6; k++) {
        float4 v = xr[lane + 32 * k];
        vals[k] = v;
        s += v.x + v.y + v.z + v.w;
        q += v.x * v.x + v.y * v.y + v.z * v.z + v.w * v.w;
    }
#pragma unroll
    for (int o = 16; o; o >>= 1) {
        s += __shfl_xor_sync(~0u, s, o);
        q += __shfl_xor_sync(~0u, q, o);
    }
    const float m = s / D_;
    const float rs = rsqrtf(q / D_ - m * m + 1e-6f);
    uint2* yo = (uint2*)(y16 + (size_t)row * D_);
    const float4* w4 = (const float4*)wv;
    const float4* b4 = (const float4*)bv;
#pragma unroll
    for (int k = 0; k < 6; k++) {
        float4 v = vals[k];
        float4 ww = w4[lane + 32 * k];
        float4 bb = b4[lane + 32 * k];
        __half2 lo = __floats2half2_rn((v.x - m) * rs * ww.x + bb.x,
                                       (v.y - m) * rs * ww.y + bb.y);
        __half2 hi = __floats2half2_rn((v.z - m) * rs * ww.z + bb.z,
                                       (v.w - m) * rs * ww.w + bb.w);
        uint2 u;
        u.x = *(uint32_t*)&lo;
        u.y = *(uint32_t*)&hi;
        yo[lane + 32 * k] = u;
    }
}

// ---------------- attention v3: HMMA with 3-product hi/lo splits ----------------
#define ASLAB 26624
#define AMMA_SMEM (6 * ASLAB)
__global__ void __launch_bounds__(256) attn_kernel(const float* __restrict__ qkv,
                                                   h16* __restrict__ o16) {
    char* sm = dynsmem;
    const uint32_t sbase = smem_u32(sm);
    const uint32_t Qh = sbase,      Ql = Qh + ASLAB;
    const uint32_t Kh = Ql + ASLAB, Kl = Kh + ASLAB;
    const uint32_t Vh = Kl + ASLAB, Vl = Vh + ASLAB;

    const int bh = blockIdx.x;
    const int b = bh / H_;
    const int h = bh % H_;
    const int tid = threadIdx.x;
    const int lane = tid & 31;
    const int w = tid >> 5;

    for (int idx = tid; idx < 208 * 32; idx += 256) {
        int m = idx >> 5, dp = idx & 31;
        float2 qv = make_float2(0.f, 0.f), kv = qv, vv = qv;
        if (m < NTOK) {
            const float* base = qkv + ((size_t)(b * NTOK + m)) * (3 * D_) + h * DH + dp * 2;
            qv = *(const float2*)(base);
            kv = *(const float2*)(base + D_);
            vv = *(const float2*)(base + 2 * D_);
        }
        uint32_t off = SW128((uint32_t)(m * 128 + dp * 4));
        h16 a0 = __float2half_rn(qv.x), a1 = __float2half_rn(qv.y);
        *(uint32_t*)(sm + (Qh - sbase) + off) = pack_h2(a0, a1);
        *(uint32_t*)(sm + (Ql - sbase) + off) =
            pack_h2(__float2half_rn(qv.x - __half2float(a0)),
                    __float2half_rn(qv.y - __half2float(a1)));
        h16 k0 = __float2half_rn(kv.x), k1 = __float2half_rn(kv.y);
        *(uint32_t*)(sm + (Kh - sbase) + off) = pack_h2(k0, k1);
        *(uint32_t*)(sm + (Kl - sbase) + off) =
            pack_h2(__float2half_rn(kv.x - __half2float(k0)),
                    __float2half_rn(kv.y - __half2float(k1)));
        h16 v0 = __float2half_rn(vv.x), v1 = __float2half_rn(vv.y);
        *(uint32_t*)(sm + (Vh - sbase) + off) = pack_h2(v0, v1);
        *(uint32_t*)(sm + (Vl - sbase) + off) =
            pack_h2(__float2half_rn(vv.x - __half2float(v0)),
                    __float2half_rn(vv.y - __half2float(v1)));
    }
    __syncthreads();

    const int c0 = (lane & 3) * 2;

    for (int mt = w; mt < 13; mt += 8) {
        float accS[26][4];
#pragma unroll
        for (int t = 0; t < 26; t++)
#pragma unroll
            for (int i = 0; i < 4; i++) accS[t][i] = 0.f;

#pragma unroll
        for (int kc = 0; kc < 4; kc++) {
            uint32_t Ah4[4], Al4[4];
            {
                uint32_t aoff = SW128((uint32_t)((mt * 16 + (lane & 15)) * 128
                                                 + (kc * 16 + (lane >> 4) * 8) * 2));
                LDSM_X4(Ah4[0], Ah4[1], Ah4[2], Ah4[3], Qh + aoff);
                LDSM_X4(Al4[0], Al4[1], Al4[2], Al4[3], Ql + aoff);
            }
            const int sub = lane >> 3, r8 = lane & 7;
            const int nloc = ((sub & 2) ? 8 : 0) + r8;
            const int kloc = kc * 16 + (sub & 1) * 8;
#pragma unroll
            for (int np = 0; np < 13; np++) {
                uint32_t boff = SW128((uint32_t)((np * 16 + nloc) * 128 + kloc * 2));
                uint32_t BH[4], BL[4];
                LDSM_X4(BH[0], BH[1], BH[2], BH[3], Kh + boff);
                LDSM_X4(BL[0], BL[1], BL[2], BL[3], Kl + boff);
                MMA16816(accS[2 * np], Ah4, BH[0], BH[1]);
                MMA16816(accS[2 * np], Ah4, BL[0], BL[1]);
                MMA16816(accS[2 * np], Al4, BH[0], BH[1]);
                MMA16816(accS[2 * np + 1], Ah4, BH[2], BH[3]);
                MMA16816(accS[2 * np + 1], Ah4, BL[2], BL[3]);
                MMA16816(accS[2 * np + 1], Al4, BH[2], BH[3]);
            }
        }

        float mx0 = -1e30f, mx1 = -1e30f;
#pragma unroll
        for (int t = 0; t < 26; t++) {
#pragma unroll
            for (int i = 0; i < 4; i++) {
                int col = t * 8 + c0 + (i & 1);
                float s = (col < NTOK) ? (accS[t][i] * 0.125f) : -1e30f;
                accS[t][i] = s;
                if (i < 2) mx0 = fmaxf(mx0, s);
                else       mx1 = fmaxf(mx1, s);
            }
        }
        mx0 = fmaxf(mx0, __shfl_xor_sync(~0u, mx0, 1));
        mx0 = fmaxf(mx0, __shfl_xor_sync(~0u, mx0, 2));
        mx1 = fmaxf(mx1, __shfl_xor_sync(~0u, mx1, 1));
        mx1 = fmaxf(mx1, __shfl_xor_sync(~0u, mx1, 2));
        float sum0 = 0.f, sum1 = 0.f;
#pragma unroll
        for (int t = 0; t < 26; t++) {
#pragma unroll
            for (int i = 0; i < 4; i++) {
                float e = expf(accS[t][i] - ((i < 2) ? mx0 : mx1));
                accS[t][i] = e;
                if (i < 2) sum0 += e;
                else       sum1 += e;
            }
        }
        sum0 += __shfl_xor_sync(~0u, sum0, 1);
        sum0 += __shfl_xor_sync(~0u, sum0, 2);
        sum1 += __shfl_xor_sync(~0u, sum1, 1);
        sum1 += __shfl_xor_sync(~0u, sum1, 2);
        const float inv0 = 1.f / sum0, inv1 = 1.f / sum1;

        float accO[8][4];
#pragma unroll
        for (int nt = 0; nt < 8; nt++)
#pragma unroll
            for (int i = 0; i < 4; i++) accO[nt][i] = 0.f;

        const int g = lane >> 3;
        const int vrow_loc = (g & 1) * 8 + (lane & 7);
        const int vcol_b = (g >> 1) * 16;

#pragma unroll
        for (int kk = 0; kk < 13; kk++) {
            float e0 = accS[2 * kk][0] * inv0, e1 = accS[2 * kk][1] * inv0;
            float e2 = accS[2 * kk][2] * inv1, e3 = accS[2 * kk][3] * inv1;
            float f0 = accS[2 * kk + 1][0] * inv0, f1 = accS[2 * kk + 1][1] * inv0;
            float f2 = accS[2 * kk + 1][2] * inv1, f3 = accS[2 * kk + 1][3] * inv1;
            h16 he0 = __float2half_rn(e0), he1 = __float2half_rn(e1);
            h16 he2 = __float2half_rn(e2), he3 = __float2half_rn(e3);
            h16 hf0 = __float2half_rn(f0), hf1 = __float2half_rn(f1);
            h16 hf2 = __float2half_rn(f2), hf3 = __float2half_rn(f3);
            uint32_t aH[4] = { pack_h2(he0, he1), pack_h2(he2, he3),
                               pack_h2(hf0, hf1), pack_h2(hf2, hf3) };
            uint32_t aL[4] = {
                pack_h2(__float2half_rn(e0 - __half2float(he0)), __float2half_rn(e1 - __half2float(he1))),
                pack_h2(__float2half_rn(e2 - __half2float(he2)), __float2half_rn(e3 - __half2float(he3))),
                pack_h2(__float2half_rn(f0 - __half2float(hf0)), __float2half_rn(f1 - __half2float(hf1))),
                pack_h2(__float2half_rn(f2 - __half2float(hf2)), __float2half_rn(f3 - __half2float(hf3))) };

            const int vrow = kk * 16 + vrow_loc;
#pragma unroll
            for (int vg = 0; vg < 4; vg++) {
                uint32_t voff = SW128((uint32_t)(vrow * 128 + vg * 32 + vcol_b));
                uint32_t VH[4], VL[4];
                LDSM_X4_T(VH[0], VH[1], VH[2], VH[3], Vh + voff);
                LDSM_X4_T(VL[0], VL[1], VL[2], VL[3], Vl + voff);
                MMA16816(accO[vg * 2], aH, VH[0], VH[1]);
                MMA16816(accO[vg * 2], aH, VL[0], VL[1]);
                MMA16816(accO[vg * 2], aL, VH[0], VH[1]);
                MMA16816(accO[vg * 2 + 1], aH, VH[2], VH[3]);
                MMA16816(accO[vg * 2 + 1], aH, VL[2], VL[3]);
                MMA16816(accO[vg * 2 + 1], aL, VH[2], VH[3]);
            }
        }

        const int r1 = mt * 16 + (lane >> 2);
        const int r2 = r1 + 8;
#pragma unroll
        for (int nt = 0; nt < 8; nt++) {
            const int col = h * DH + nt * 8 + c0;
            if (r1 < NTOK) {
                __half2 v = __floats2half2_rn(accO[nt][0], accO[nt][1]);
                *(uint32_t*)(o16 + (size_t)(b * NTOK + r1) * D_ + col) = *(uint32_t*)&v;
            }
            if (r2 < NTOK) {
                __half2 v = __floats2half2_rn(accO[nt][2], accO[nt][3]);
                *(uint32_t*)(o16 + (size_t)(b * NTOK + r2) * D_ + col) = *(uint32_t*)&v;
            }
        }
    }
}

// ---------------- host ----------------
extern "C" void kernel_launch(void* const* d_in, const int* in_sizes, int n_in,
                              void* d_out, int out_size) {
    const float* x       = (const float*)d_in[0];
    const float* conv_w  = (const float*)d_in[1];
    const float* conv_b  = (const float*)d_in[2];
    const float* cls_tok = (const float*)d_in[3];
    const float* pos     = (const float*)d_in[4];
    const float* ln1w    = (const float*)d_in[5];
    const float* ln1b    = (const float*)d_in[6];
    const float* qkvw    = (const float*)d_in[7];
    const float* qkvb    = (const float*)d_in[8];
    const float* projw   = (const float*)d_in[9];
    const float* projb   = (const float*)d_in[10];
    const float* ln2w    = (const float*)d_in[11];
    const float* ln2b    = (const float*)d_in[12];
    const float* fc1w    = (const float*)d_in[13];
    const float* fc1b    = (const float*)d_in[14];
    const float* fc2w    = (const float*)d_in[15];
    const float* fc2b    = (const float*)d_in[16];
    const float* lnfw    = (const float*)d_in[17];
    const float* lnfb    = (const float*)d_in[18];

    float *emb, *h, *qkv;
    h16 *p16, *cw16, *y16, *o16, *mid16;
    h16 *wq, *wp, *w1, *w2;
    cudaGetSymbolAddress((void**)&emb,   g_emb);
    cudaGetSymbolAddress((void**)&h,     g_h);
    cudaGetSymbolAddress((void**)&qkv,   g_qkv);
    cudaGetSymbolAddress((void**)&p16,   g_p16);
    cudaGetSymbolAddress((void**)&cw16,  g_cw16);
    cudaGetSymbolAddress((void**)&y16,   g_y16);
    cudaGetSymbolAddress((void**)&o16,   g_o16);
    cudaGetSymbolAddress((void**)&mid16, g_mid16);
    cudaGetSymbolAddress((void**)&wq,    g_wqkv);
    cudaGetSymbolAddress((void**)&wp,    g_wproj);
    cudaGetSymbolAddress((void**)&w1,    g_wfc1);
    cudaGetSymbolAddress((void**)&w2,    g_wfc2);

    cudaFuncSetAttribute(attn_kernel, cudaFuncAttributeMaxDynamicSharedMemorySize, AMMA_SMEM);
    cudaFuncSetAttribute(gemm_mma_kernel, cudaFuncAttributeMaxDynamicSharedMemorySize, GSMEM_SZ);

    // ---- weight conversion (transpose + fp16), batched over layers ----
    {
        dim3 blk(32, 8);
        wsplit_all_kernel<<<dim3(3 * D_ / 32, D_ / 32, L_), blk>>>(qkvw, wq, D_, 3 * D_);
        wsplit_all_kernel<<<dim3(D_ / 32, D_ / 32, L_), blk>>>(projw, wp, D_, D_);
        wsplit_all_kernel<<<dim3(F_ / 32, D_ / 32, L_), blk>>>(fc1w, w1, D_, F_);
        wsplit_all_kernel<<<dim3(D_ / 32, F_ / 32, L_), blk>>>(fc2w, w2, F_, D_);
        split_kernel<<<1024, 256>>>(conv_w, cw16, D_ * D_);
    }

    // ---- patch embed (tensor core) ----
    extract_patches_kernel<<<2048, 256>>>(x, p16);
    gemm_mma_kernel<<<dim3(D_ / 128, (PROWS + 127) / 128), 256, GSMEM_SZ>>>(
        p16, cw16, conv_b, emb, nullptr, nullptr, PROWS, D_, D_, 0);
    assemble_kernel<<<2048, 256>>>(emb, cls_tok, pos, h);

    const int mb = (ROWS + 127) / 128;   // 50
    const int lnb = (ROWS + 7) / 8;      // 788
    for (int l = 0; l < L_; l++) {
        ln_h_warp_kernel<<<lnb, 256>>>(h, ln1w + l * D_, ln1b + l * D_, y16, ROWS);
        gemm_mma_kernel<<<dim3(3 * D_ / 128, mb), 256, GSMEM_SZ>>>(
            y16, wq + (size_t)l * 3 * D_ * D_, qkvb + (size_t)l * 3 * D_,
            qkv, nullptr, nullptr, ROWS, 3 * D_, D_, 0);
        attn_kernel<<<B_ * H_, 256, AMMA_SMEM>>>(qkv, o16);
        gemm_mma_kernel<<<dim3(D_ / 128, mb), 256, GSMEM_SZ>>>(
            o16, wp + (size_t)l * D_ * D_, projb + (size_t)l * D_,
            nullptr, h, nullptr, ROWS, D_, D_, 1);
        ln_h_warp_kernel<<<lnb, 256>>>(h, ln2w + l * D_, ln2b + l * D_, y16, ROWS);
        gemm_mma_kernel<<<dim3(F_ / 128, mb), 256, GSMEM_SZ>>>(
            y16, w1 + (size_t)l * F_ * D_, fc1b + (size_t)l * F_,
            nullptr, nullptr, mid16, ROWS, F_, D_, 2);
        gemm_mma_kernel<<<dim3(D_ / 128, mb), 256, GSMEM_SZ>>>(
            mid16, w2 + (size_t)l * D_ * F_, fc2b + (size_t)l * D_,
            nullptr, h, nullptr, ROWS, D_, F_, 1);
    }

    ln_kernel<<<B_, 256>>>(h, lnfw, lnfb, (float*)d_out, D_, NTOK * D_, D_);
}